// round 9
// baseline (speedup 1.0000x reference)
#include <cuda_runtime.h>
#include <cuda_bf16.h>
#include <cstdint>

// Shapes (fixed)
#define TQDIM 4096
#define TKDIM 4096
#define DMODEL 2048
#define NHEADS 4
#define ROWS 8192  // B*T

// Pre-split inputs (hi/lo bf16)
__device__ __nv_bfloat16 g_xqh[ROWS * DMODEL];
__device__ __nv_bfloat16 g_xql[ROWS * DMODEL];
__device__ __nv_bfloat16 g_xkh[ROWS * DMODEL];
__device__ __nv_bfloat16 g_xkl[ROWS * DMODEL];
__device__ __nv_bfloat16 g_Wth[320 * DMODEL];  // [n][k]; n<256: Wq col, n>=256: Wk col
__device__ __nv_bfloat16 g_Wtl[320 * DMODEL];
// Projection outputs (hi/lo bf16); q head-major [h][row][64]
__device__ __nv_bfloat16 g_qIh[NHEADS * ROWS * 64];
__device__ __nv_bfloat16 g_qIl[NHEADS * ROWS * 64];
__device__ __nv_bfloat16 g_kIh[ROWS * 64];
__device__ __nv_bfloat16 g_kIl[ROWS * 64];
__device__ float g_wI[ROWS * 4];

// ---------------------------------------------------------------------------
// helpers
// ---------------------------------------------------------------------------
__device__ __forceinline__ void split1(float v, __nv_bfloat16& h,
                                       __nv_bfloat16& l) {
  h = __float2bfloat16(v);
  l = __float2bfloat16(v - __bfloat162float(h));
}
__device__ __forceinline__ uint32_t pack2(__nv_bfloat16 a, __nv_bfloat16 b) {
  return (uint32_t)__bfloat16_as_ushort(a) |
         ((uint32_t)__bfloat16_as_ushort(b) << 16);
}
__device__ __forceinline__ void split_f4(float4 v, uint2& hi, uint2& lo) {
  __nv_bfloat16 h0, l0, h1, l1, h2, l2, h3, l3;
  split1(v.x, h0, l0); split1(v.y, h1, l1);
  split1(v.z, h2, l2); split1(v.w, h3, l3);
  hi.x = pack2(h0, h1); hi.y = pack2(h2, h3);
  lo.x = pack2(l0, l1); lo.y = pack2(l2, l3);
}

__device__ __forceinline__ void mma_bf16(float* c, const uint32_t* a,
                                         uint32_t b0, uint32_t b1) {
  asm volatile(
      "mma.sync.aligned.m16n8k16.row.col.f32.bf16.bf16.f32 "
      "{%0,%1,%2,%3}, {%4,%5,%6,%7}, {%8,%9}, {%0,%1,%2,%3};\n"
      : "+f"(c[0]), "+f"(c[1]), "+f"(c[2]), "+f"(c[3])
      : "r"(a[0]), "r"(a[1]), "r"(a[2]), "r"(a[3]), "r"(b0), "r"(b1));
}

__device__ __forceinline__ void ldmx4(uint32_t* r, const void* p) {
  uint32_t a = (uint32_t)__cvta_generic_to_shared(p);
  asm volatile(
      "ldmatrix.sync.aligned.m8n8.x4.shared.b16 {%0,%1,%2,%3}, [%4];"
      : "=r"(r[0]), "=r"(r[1]), "=r"(r[2]), "=r"(r[3])
      : "r"(a));
}

__device__ __forceinline__ void cp16(void* dst, const void* src) {
  uint32_t d = (uint32_t)__cvta_generic_to_shared(dst);
  asm volatile("cp.async.cg.shared.global [%0], [%1], 16;" :: "r"(d), "l"(src));
}
#define CP_COMMIT() asm volatile("cp.async.commit_group;" ::: "memory")
#define CP_WAIT(n) asm volatile("cp.async.wait_group %0;" :: "n"(n) : "memory")

// ---------------------------------------------------------------------------
// x_q convert (hi/lo split) fused with w_I = x_q @ Ww. One warp per row.
// ---------------------------------------------------------------------------
__global__ __launch_bounds__(256) void convq_kernel(
    const float* __restrict__ x, const float* __restrict__ Ww,
    __nv_bfloat16* __restrict__ xh, __nv_bfloat16* __restrict__ xl,
    float* __restrict__ wI) {
  int row = blockIdx.x * 8 + (threadIdx.x >> 5);
  int lane = threadIdx.x & 31;
  const float4* xr = (const float4*)(x + (size_t)row * DMODEL);
  uint2* oh = (uint2*)(xh + (size_t)row * DMODEL);
  uint2* ol = (uint2*)(xl + (size_t)row * DMODEL);
  float a0 = 0.f, a1 = 0.f, a2 = 0.f, a3 = 0.f;
#pragma unroll
  for (int i = 0; i < 16; i++) {
    int d4 = lane + i * 32;
    float4 v = xr[d4];
    uint2 hi, lo;
    split_f4(v, hi, lo);
    oh[d4] = hi;
    ol[d4] = lo;
    int d = d4 * 4;
    float4 w;
    w = *(const float4*)&Ww[(d + 0) * 4];
    a0 = fmaf(v.x, w.x, a0); a1 = fmaf(v.x, w.y, a1);
    a2 = fmaf(v.x, w.z, a2); a3 = fmaf(v.x, w.w, a3);
    w = *(const float4*)&Ww[(d + 1) * 4];
    a0 = fmaf(v.y, w.x, a0); a1 = fmaf(v.y, w.y, a1);
    a2 = fmaf(v.y, w.z, a2); a3 = fmaf(v.y, w.w, a3);
    w = *(const float4*)&Ww[(d + 2) * 4];
    a0 = fmaf(v.z, w.x, a0); a1 = fmaf(v.z, w.y, a1);
    a2 = fmaf(v.z, w.z, a2); a3 = fmaf(v.z, w.w, a3);
    w = *(const float4*)&Ww[(d + 3) * 4];
    a0 = fmaf(v.w, w.x, a0); a1 = fmaf(v.w, w.y, a1);
    a2 = fmaf(v.w, w.z, a2); a3 = fmaf(v.w, w.w, a3);
  }
#pragma unroll
  for (int off = 16; off; off >>= 1) {
    a0 += __shfl_down_sync(0xffffffffu, a0, off);
    a1 += __shfl_down_sync(0xffffffffu, a1, off);
    a2 += __shfl_down_sync(0xffffffffu, a2, off);
    a3 += __shfl_down_sync(0xffffffffu, a3, off);
  }
  if (lane == 0) *(float4*)&wI[(size_t)row * 4] = make_float4(a0, a1, a2, a3);
}

__global__ __launch_bounds__(256) void convert_kernel(
    const float* __restrict__ x, __nv_bfloat16* __restrict__ xh,
    __nv_bfloat16* __restrict__ xl, int n4) {
  int i = blockIdx.x * blockDim.x + threadIdx.x;
  if (i < n4) {
    float4 v = ((const float4*)x)[i];
    uint2 hi, lo;
    split_f4(v, hi, lo);
    ((uint2*)xh)[i] = hi;
    ((uint2*)xl)[i] = lo;
  }
}

// W transpose+split: Wt[n][k] = W[k][n]
__global__ __launch_bounds__(256) void wt_kernel(
    const float* __restrict__ Wq, const float* __restrict__ Wk,
    __nv_bfloat16* __restrict__ Wth, __nv_bfloat16* __restrict__ Wtl) {
  int k = blockIdx.x * 256 + threadIdx.x;
  int n = blockIdx.y;
  float v = (n < 256) ? Wq[(size_t)k * 256 + n] : Wk[(size_t)k * 64 + (n - 256)];
  __nv_bfloat16 h, l;
  split1(v, h, l);
  Wth[(size_t)n * DMODEL + k] = h;
  Wtl[(size_t)n * DMODEL + k] = l;
}

// ---------------------------------------------------------------------------
// Projection: C = A @ Wt^T (pre-split bf16), bf16x3 HMMA.
// CTA 128 x 64, 8 warps as 4x2 (warp 32x32), K-chunk 64, 2-stage cp.async,
// 2 CTAs/SM, grid 320 uniform tiles.
// blocks 0..255: q (m0=(bx>>2)*128, ncols (bx&3)*64); 256..319: k.
// ---------------------------------------------------------------------------
#define PSP 72                    // halves stride (144 B)
#define PAB (128 * PSP * 2)       // 18432 per A subtile
#define PBB (64 * PSP * 2)        // 9216 per B subtile
#define PSTG (2 * PAB + 2 * PBB)  // 55296
#define PROJ_SMEM (2 * PSTG)      // 110592

__global__ __launch_bounds__(256, 2) void proj_kernel() {
  extern __shared__ __align__(16) char smem[];
  const int bx = blockIdx.x;
  const bool isQ = bx < 256;
  const int m0 = isQ ? (bx >> 2) * 128 : (bx - 256) * 128;
  const int nb = isQ ? (bx & 3) * 64 : 256;  // Wt row base

  const __nv_bfloat16* Ahs = isQ ? g_xqh : g_xkh;
  const __nv_bfloat16* Als = isQ ? g_xql : g_xkl;

  const int tid = threadIdx.x, wid = tid >> 5, lane = tid & 31;
  const int g = lane >> 2, q4 = lane & 3;
  const int mwarp = (wid >> 1) * 32, nwarp = (wid & 1) * 32;

  const int aRow = (lane & 7) + (lane & 8);
  const int aCol = (lane & 16) ? 8 : 0;
  const int bRow = (lane & 7) + ((lane & 16) ? 8 : 0);
  const int bCol = (lane & 8) ? 8 : 0;

  auto issue = [&](int kc) {
    char* st = smem + (kc & 1) * PSTG;
#pragma unroll
    for (int l = 0; l < 4; l++) {
      int idx = tid + l * 256, m = idx >> 3, c = idx & 7;
      size_t src = (size_t)(m0 + m) * DMODEL + kc * 64 + c * 8;
      cp16(st + m * 144 + c * 16, Ahs + src);
      cp16(st + PAB + m * 144 + c * 16, Als + src);
    }
#pragma unroll
    for (int l = 0; l < 2; l++) {
      int idx = tid + l * 256, n = idx >> 3, c = idx & 7;
      size_t src = (size_t)(nb + n) * DMODEL + kc * 64 + c * 8;
      cp16(st + 2 * PAB + n * 144 + c * 16, g_Wth + src);
      cp16(st + 2 * PAB + PBB + n * 144 + c * 16, g_Wtl + src);
    }
    CP_COMMIT();
  };

  issue(0);
  issue(1);

  float dot[2][4][4] = {};
  const int NKC = DMODEL / 64;  // 32

  for (int kc = 0; kc < NKC; kc++) {
    if (kc + 1 < NKC) { CP_WAIT(1); } else { CP_WAIT(0); }
    __syncthreads();
    const char* st = smem + (kc & 1) * PSTG;
    const __nv_bfloat16* Ah = (const __nv_bfloat16*)st;
    const __nv_bfloat16* Al = (const __nv_bfloat16*)(st + PAB);
    const __nv_bfloat16* Bh = (const __nv_bfloat16*)(st + 2 * PAB);
    const __nv_bfloat16* Bl = (const __nv_bfloat16*)(st + 2 * PAB + PBB);

#pragma unroll
    for (int ks = 0; ks < 4; ks++) {
      uint32_t ah[2][4], al[2][4];
#pragma unroll
      for (int mf = 0; mf < 2; mf++) {
        ldmx4(ah[mf], Ah + (mwarp + mf * 16 + aRow) * PSP + ks * 16 + aCol);
        ldmx4(al[mf], Al + (mwarp + mf * 16 + aRow) * PSP + ks * 16 + aCol);
      }
#pragma unroll
      for (int p = 0; p < 2; p++) {
        uint32_t bh[4], bl[4];
        ldmx4(bh, Bh + (nwarp + p * 16 + bRow) * PSP + ks * 16 + bCol);
        ldmx4(bl, Bl + (nwarp + p * 16 + bRow) * PSP + ks * 16 + bCol);
#pragma unroll
        for (int mf = 0; mf < 2; mf++) {
          mma_bf16(dot[mf][2 * p], ah[mf], bh[0], bh[1]);
          mma_bf16(dot[mf][2 * p], ah[mf], bl[0], bl[1]);
          mma_bf16(dot[mf][2 * p], al[mf], bh[0], bh[1]);
          mma_bf16(dot[mf][2 * p + 1], ah[mf], bh[2], bh[3]);
          mma_bf16(dot[mf][2 * p + 1], ah[mf], bl[2], bl[3]);
          mma_bf16(dot[mf][2 * p + 1], al[mf], bh[2], bh[3]);
        }
      }
    }
    __syncthreads();
    if (kc + 2 < NKC) issue(kc + 2);
  }

  // epilogue: split to hi/lo bf16 and write
#pragma unroll
  for (int mf = 0; mf < 2; mf++) {
#pragma unroll
    for (int nf = 0; nf < 4; nf++) {
      int grow = m0 + mwarp + mf * 16 + g;
      __nv_bfloat16 h0, l0, h1, l1;
      if (isQ) {
        int ncol = nb + nwarp + nf * 8 + q4 * 2;  // global Wq col (0..255)
        int head = ncol >> 6, hcol = ncol & 63;
        __nv_bfloat16* Oh = g_qIh + ((size_t)head * ROWS + grow) * 64 + hcol;
        __nv_bfloat16* Ol = g_qIl + ((size_t)head * ROWS + grow) * 64 + hcol;
        split1(dot[mf][nf][0], h0, l0);
        split1(dot[mf][nf][1], h1, l1);
        *(uint32_t*)Oh = pack2(h0, h1);
        *(uint32_t*)Ol = pack2(l0, l1);
        split1(dot[mf][nf][2], h0, l0);
        split1(dot[mf][nf][3], h1, l1);
        *(uint32_t*)(Oh + 8 * 64) = pack2(h0, h1);
        *(uint32_t*)(Ol + 8 * 64) = pack2(l0, l1);
      } else {
        int ncol = nwarp + nf * 8 + q4 * 2;
        __nv_bfloat16* Oh = g_kIh + (size_t)grow * 64 + ncol;
        __nv_bfloat16* Ol = g_kIl + (size_t)grow * 64 + ncol;
        split1(dot[mf][nf][0], h0, l0);
        split1(dot[mf][nf][1], h1, l1);
        *(uint32_t*)Oh = pack2(h0, h1);
        *(uint32_t*)Ol = pack2(l0, l1);
        split1(dot[mf][nf][2], h0, l0);
        split1(dot[mf][nf][3], h1, l1);
        *(uint32_t*)(Oh + 8 * 64) = pack2(h0, h1);
        *(uint32_t*)(Ol + 8 * 64) = pack2(l0, l1);
      }
    }
  }
}

// ---------------------------------------------------------------------------
// Main: CTA 128q x 64k, 8 warps (4x2), warp 32x32, 2 CTAs/SM.
// A (q head) hi/lo double-buffered cp.async; B (k) fixed; per head:
// dot (bf16x3) -> relu -> w-weighted accumulate.
// ---------------------------------------------------------------------------
#define MSP 72
#define MAB (128 * MSP * 2)                 // 18432
#define MBB (64 * MSP * 2)                  // 9216
#define M_B (4 * MAB)
#define M_WS (4 * MAB + 2 * MBB)
#define MAIN_SMEM (4 * MAB + 2 * MBB + 2048)  // 94208

__global__ __launch_bounds__(256, 2) void main_mma_kernel(
    const float* __restrict__ wI, float* __restrict__ out) {
  extern __shared__ __align__(16) char smem[];
  float* ws = (float*)(smem + M_WS);

  const int tid = threadIdx.x, wid = tid >> 5, lane = tid & 31;
  const int g = lane >> 2, q4 = lane & 3;
  const int mwarp = (wid >> 1) * 32, nwarp = (wid & 1) * 32;
  const int b = blockIdx.z, q0 = blockIdx.y * 128, k0 = blockIdx.x * 64;

  const int aRow = (lane & 7) + (lane & 8);
  const int aCol = (lane & 16) ? 8 : 0;
  const int bRow = (lane & 7) + ((lane & 16) ? 8 : 0);
  const int bCol = (lane & 8) ? 8 : 0;

  auto issueA = [&](int h) {
    char* st = smem + (h & 1) * 2 * MAB;
    size_t base = ((size_t)h * ROWS + b * TQDIM + q0) * 64;
#pragma unroll
    for (int l = 0; l < 4; l++) {
      int idx = tid + l * 256, m = idx >> 3, c = idx & 7;
      cp16(st + m * 144 + c * 16, g_qIh + base + (size_t)m * 64 + c * 8);
      cp16(st + MAB + m * 144 + c * 16, g_qIl + base + (size_t)m * 64 + c * 8);
    }
  };

  // prologue: group0 = B + A(0); group1 = A(1)
  {
    char* st = smem + M_B;
    size_t base = ((size_t)b * TKDIM + k0) * 64;
#pragma unroll
    for (int l = 0; l < 2; l++) {
      int idx = tid + l * 256, m = idx >> 3, c = idx & 7;
      cp16(st + m * 144 + c * 16, g_kIh + base + (size_t)m * 64 + c * 8);
      cp16(st + MBB + m * 144 + c * 16, g_kIl + base + (size_t)m * 64 + c * 8);
    }
  }
  issueA(0);
  CP_COMMIT();
  issueA(1);
  CP_COMMIT();
  if (tid < 128)
    *(float4*)&ws[tid * 4] =
        *(const float4*)&wI[(size_t)(b * TQDIM + q0 + tid) * 4];

  const __nv_bfloat16* Bh = (const __nv_bfloat16*)(smem + M_B);
  const __nv_bfloat16* Bl = (const __nv_bfloat16*)(smem + M_B + MBB);

  float acc[2][4][4] = {};

  for (int h = 0; h < NHEADS; h++) {
    if (h + 1 < NHEADS) { CP_WAIT(1); } else { CP_WAIT(0); }
    __syncthreads();
    const __nv_bfloat16* Ah = (const __nv_bfloat16*)(smem + (h & 1) * 2 * MAB);
    const __nv_bfloat16* Al = (const __nv_bfloat16*)((const char*)Ah + MAB);

    float dot[2][4][4] = {};
#pragma unroll
    for (int ks = 0; ks < 4; ks++) {
      uint32_t ah[2][4], al[2][4];
#pragma unroll
      for (int mf = 0; mf < 2; mf++) {
        ldmx4(ah[mf], Ah + (mwarp + mf * 16 + aRow) * MSP + ks * 16 + aCol);
        ldmx4(al[mf], Al + (mwarp + mf * 16 + aRow) * MSP + ks * 16 + aCol);
      }
#pragma unroll
      for (int p = 0; p < 2; p++) {
        uint32_t bh[4], bl[4];
        ldmx4(bh, Bh + (nwarp + p * 16 + bRow) * MSP + ks * 16 + bCol);
        ldmx4(bl, Bl + (nwarp + p * 16 + bRow) * MSP + ks * 16 + bCol);
#pragma unroll
        for (int mf = 0; mf < 2; mf++) {
          mma_bf16(dot[mf][2 * p], ah[mf], bh[0], bh[1]);
          mma_bf16(dot[mf][2 * p], ah[mf], bl[0], bl[1]);
          mma_bf16(dot[mf][2 * p], al[mf], bh[0], bh[1]);
          mma_bf16(dot[mf][2 * p + 1], ah[mf], bh[2], bh[3]);
          mma_bf16(dot[mf][2 * p + 1], ah[mf], bl[2], bl[3]);
          mma_bf16(dot[mf][2 * p + 1], al[mf], bh[2], bh[3]);
        }
      }
    }
    // relu + weighted accumulate
#pragma unroll
    for (int mf = 0; mf < 2; mf++) {
      float wa = ws[(mwarp + mf * 16 + g) * 4 + h];
      float wb = ws[(mwarp + mf * 16 + g + 8) * 4 + h];
#pragma unroll
      for (int nf = 0; nf < 4; nf++) {
        acc[mf][nf][0] = fmaf(wa, fmaxf(dot[mf][nf][0], 0.f), acc[mf][nf][0]);
        acc[mf][nf][1] = fmaf(wa, fmaxf(dot[mf][nf][1], 0.f), acc[mf][nf][1]);
        acc[mf][nf][2] = fmaf(wb, fmaxf(dot[mf][nf][2], 0.f), acc[mf][nf][2]);
        acc[mf][nf][3] = fmaf(wb, fmaxf(dot[mf][nf][3], 0.f), acc[mf][nf][3]);
      }
    }
    if (h + 2 < NHEADS) {
      __syncthreads();  // all warps done with buf (h&1)
      issueA(h + 2);
      CP_COMMIT();
    }
  }

  float* obase = out + (size_t)(b * TQDIM + q0) * TKDIM + k0;
#pragma unroll
  for (int mf = 0; mf < 2; mf++) {
    int r0 = mwarp + mf * 16 + g;
#pragma unroll
    for (int nf = 0; nf < 4; nf++) {
      int col = nwarp + nf * 8 + q4 * 2;
      *(float2*)&obase[(size_t)r0 * TKDIM + col] =
          make_float2(acc[mf][nf][0], acc[mf][nf][1]);
      *(float2*)&obase[(size_t)(r0 + 8) * TKDIM + col] =
          make_float2(acc[mf][nf][2], acc[mf][nf][3]);
    }
  }
}

// ---------------------------------------------------------------------------
extern "C" void kernel_launch(void* const* d_in, const int* in_sizes, int n_in,
                              void* d_out, int out_size) {
  const float* x_q = (const float*)d_in[0];
  const float* x_k = (const float*)d_in[1];
  const float* Wq = (const float*)d_in[2];
  const float* Ww = (const float*)d_in[3];
  const float* Wk = (const float*)d_in[4];
  float* out = (float*)d_out;

  __nv_bfloat16 *xqh, *xql, *xkh, *xkl, *Wth, *Wtl;
  float* wI;
  cudaGetSymbolAddress((void**)&xqh, g_xqh);
  cudaGetSymbolAddress((void**)&xql, g_xql);
  cudaGetSymbolAddress((void**)&xkh, g_xkh);
  cudaGetSymbolAddress((void**)&xkl, g_xkl);
  cudaGetSymbolAddress((void**)&Wth, g_Wth);
  cudaGetSymbolAddress((void**)&Wtl, g_Wtl);
  cudaGetSymbolAddress((void**)&wI, g_wI);

  cudaFuncSetAttribute(proj_kernel, cudaFuncAttributeMaxDynamicSharedMemorySize,
                       PROJ_SMEM);
  cudaFuncSetAttribute(main_mma_kernel,
                       cudaFuncAttributeMaxDynamicSharedMemorySize, MAIN_SMEM);

  const int n4 = ROWS * DMODEL / 4;
  convq_kernel<<<ROWS / 8, 256>>>(x_q, Ww, xqh, xql, wI);
  convert_kernel<<<n4 / 256, 256>>>(x_k, xkh, xkl, n4);
  wt_kernel<<<dim3(DMODEL / 256, 320), 256>>>(Wq, Wk, Wth, Wtl);
  proj_kernel<<<320, 256, PROJ_SMEM>>>();
  main_mma_kernel<<<dim3(TKDIM / 64, TQDIM / 128, 2), 256, MAIN_SMEM>>>(wI,
                                                                        out);
}

// round 10
// speedup vs baseline: 1.0271x; 1.0271x over previous
#include <cuda_runtime.h>
#include <cuda_bf16.h>
#include <cstdint>

// Shapes (fixed)
#define TQDIM 4096
#define TKDIM 4096
#define DMODEL 2048
#define NHEADS 4
#define ROWS 8192  // B*T

// Pre-split inputs (hi/lo bf16)
__device__ __nv_bfloat16 g_xqh[ROWS * DMODEL];
__device__ __nv_bfloat16 g_xql[ROWS * DMODEL];
__device__ __nv_bfloat16 g_xkh[ROWS * DMODEL];
__device__ __nv_bfloat16 g_xkl[ROWS * DMODEL];
__device__ __nv_bfloat16 g_Wth[320 * DMODEL];  // [n][k]; n<256: Wq col, n>=256: Wk col
__device__ __nv_bfloat16 g_Wtl[320 * DMODEL];
// Projection outputs (hi/lo bf16); q head-major [h][row][64]
__device__ __nv_bfloat16 g_qIh[NHEADS * ROWS * 64];
__device__ __nv_bfloat16 g_qIl[NHEADS * ROWS * 64];
__device__ __nv_bfloat16 g_kIh[ROWS * 64];
__device__ __nv_bfloat16 g_kIl[ROWS * 64];
__device__ float g_wI[ROWS * 4];

// ---------------------------------------------------------------------------
// helpers
// ---------------------------------------------------------------------------
__device__ __forceinline__ void split1(float v, __nv_bfloat16& h,
                                       __nv_bfloat16& l) {
  h = __float2bfloat16(v);
  l = __float2bfloat16(v - __bfloat162float(h));
}
__device__ __forceinline__ uint32_t pack2(__nv_bfloat16 a, __nv_bfloat16 b) {
  return (uint32_t)__bfloat16_as_ushort(a) |
         ((uint32_t)__bfloat16_as_ushort(b) << 16);
}
__device__ __forceinline__ void split_f4(float4 v, uint2& hi, uint2& lo) {
  __nv_bfloat16 h0, l0, h1, l1, h2, l2, h3, l3;
  split1(v.x, h0, l0); split1(v.y, h1, l1);
  split1(v.z, h2, l2); split1(v.w, h3, l3);
  hi.x = pack2(h0, h1); hi.y = pack2(h2, h3);
  lo.x = pack2(l0, l1); lo.y = pack2(l2, l3);
}

__device__ __forceinline__ void mma_bf16(float* c, const uint32_t* a,
                                         uint32_t b0, uint32_t b1) {
  asm volatile(
      "mma.sync.aligned.m16n8k16.row.col.f32.bf16.bf16.f32 "
      "{%0,%1,%2,%3}, {%4,%5,%6,%7}, {%8,%9}, {%0,%1,%2,%3};\n"
      : "+f"(c[0]), "+f"(c[1]), "+f"(c[2]), "+f"(c[3])
      : "r"(a[0]), "r"(a[1]), "r"(a[2]), "r"(a[3]), "r"(b0), "r"(b1));
}

__device__ __forceinline__ void ldmx4(uint32_t* r, const void* p) {
  uint32_t a = (uint32_t)__cvta_generic_to_shared(p);
  asm volatile(
      "ldmatrix.sync.aligned.m8n8.x4.shared.b16 {%0,%1,%2,%3}, [%4];"
      : "=r"(r[0]), "=r"(r[1]), "=r"(r[2]), "=r"(r[3])
      : "r"(a));
}

__device__ __forceinline__ void cp16(void* dst, const void* src) {
  uint32_t d = (uint32_t)__cvta_generic_to_shared(dst);
  asm volatile("cp.async.cg.shared.global [%0], [%1], 16;" :: "r"(d), "l"(src));
}
#define CP_COMMIT() asm volatile("cp.async.commit_group;" ::: "memory")
#define CP_WAIT(n) asm volatile("cp.async.wait_group %0;" :: "n"(n) : "memory")

// ---------------------------------------------------------------------------
// x_q convert (hi/lo split) fused with w_I = x_q @ Ww. One warp per row.
// ---------------------------------------------------------------------------
__global__ __launch_bounds__(256) void convq_kernel(
    const float* __restrict__ x, const float* __restrict__ Ww,
    __nv_bfloat16* __restrict__ xh, __nv_bfloat16* __restrict__ xl,
    float* __restrict__ wI) {
  int row = blockIdx.x * 8 + (threadIdx.x >> 5);
  int lane = threadIdx.x & 31;
  const float4* xr = (const float4*)(x + (size_t)row * DMODEL);
  uint2* oh = (uint2*)(xh + (size_t)row * DMODEL);
  uint2* ol = (uint2*)(xl + (size_t)row * DMODEL);
  float a0 = 0.f, a1 = 0.f, a2 = 0.f, a3 = 0.f;
#pragma unroll
  for (int i = 0; i < 16; i++) {
    int d4 = lane + i * 32;
    float4 v = xr[d4];
    uint2 hi, lo;
    split_f4(v, hi, lo);
    oh[d4] = hi;
    ol[d4] = lo;
    int d = d4 * 4;
    float4 w;
    w = *(const float4*)&Ww[(d + 0) * 4];
    a0 = fmaf(v.x, w.x, a0); a1 = fmaf(v.x, w.y, a1);
    a2 = fmaf(v.x, w.z, a2); a3 = fmaf(v.x, w.w, a3);
    w = *(const float4*)&Ww[(d + 1) * 4];
    a0 = fmaf(v.y, w.x, a0); a1 = fmaf(v.y, w.y, a1);
    a2 = fmaf(v.y, w.z, a2); a3 = fmaf(v.y, w.w, a3);
    w = *(const float4*)&Ww[(d + 2) * 4];
    a0 = fmaf(v.z, w.x, a0); a1 = fmaf(v.z, w.y, a1);
    a2 = fmaf(v.z, w.z, a2); a3 = fmaf(v.z, w.w, a3);
    w = *(const float4*)&Ww[(d + 3) * 4];
    a0 = fmaf(v.w, w.x, a0); a1 = fmaf(v.w, w.y, a1);
    a2 = fmaf(v.w, w.z, a2); a3 = fmaf(v.w, w.w, a3);
  }
#pragma unroll
  for (int off = 16; off; off >>= 1) {
    a0 += __shfl_down_sync(0xffffffffu, a0, off);
    a1 += __shfl_down_sync(0xffffffffu, a1, off);
    a2 += __shfl_down_sync(0xffffffffu, a2, off);
    a3 += __shfl_down_sync(0xffffffffu, a3, off);
  }
  if (lane == 0) *(float4*)&wI[(size_t)row * 4] = make_float4(a0, a1, a2, a3);
}

__global__ __launch_bounds__(256) void convert_kernel(
    const float* __restrict__ x, __nv_bfloat16* __restrict__ xh,
    __nv_bfloat16* __restrict__ xl, int n4) {
  int i = blockIdx.x * blockDim.x + threadIdx.x;
  if (i < n4) {
    float4 v = ((const float4*)x)[i];
    uint2 hi, lo;
    split_f4(v, hi, lo);
    ((uint2*)xh)[i] = hi;
    ((uint2*)xl)[i] = lo;
  }
}

// W transpose+split: Wt[n][k] = W[k][n]
__global__ __launch_bounds__(256) void wt_kernel(
    const float* __restrict__ Wq, const float* __restrict__ Wk,
    __nv_bfloat16* __restrict__ Wth, __nv_bfloat16* __restrict__ Wtl) {
  int k = blockIdx.x * 256 + threadIdx.x;
  int n = blockIdx.y;
  float v = (n < 256) ? Wq[(size_t)k * 256 + n] : Wk[(size_t)k * 64 + (n - 256)];
  __nv_bfloat16 h, l;
  split1(v, h, l);
  Wth[(size_t)n * DMODEL + k] = h;
  Wtl[(size_t)n * DMODEL + k] = l;
}

// ---------------------------------------------------------------------------
// Projection: C = A @ Wt^T (pre-split bf16), bf16x3 HMMA.
// CTA 64 x 64, 4 warps (2x2 of 32x32), K-chunk 32, 2-stage cp.async,
// 4 CTAs/SM (smem 40KB, regs<=128). Grid 640 uniform tiles:
//  blocks 0..511: q (m0=(bx>>2)*64, nb=(bx&3)*64); 512..639: k (nb=256).
// ---------------------------------------------------------------------------
#define PSP 40                    // halves stride (80 B, 16B-aligned rows)
#define PSUB (64 * 80)            // 5120 B per subtile (64 rows x 80B)
#define PSTG (4 * PSUB)           // 20480: Ah, Al, Bh, Bl
#define PROJ_SMEM (2 * PSTG)      // 40960

__global__ __launch_bounds__(128, 4) void proj_kernel() {
  extern __shared__ __align__(16) char smem[];
  const int bx = blockIdx.x;
  const bool isQ = bx < 512;
  const int m0 = isQ ? (bx >> 2) * 64 : (bx - 512) * 64;
  const int nb = isQ ? (bx & 3) * 64 : 256;  // Wt row base

  const __nv_bfloat16* Ahs = isQ ? g_xqh : g_xkh;
  const __nv_bfloat16* Als = isQ ? g_xql : g_xkl;

  const int tid = threadIdx.x, wid = tid >> 5, lane = tid & 31;
  const int g = lane >> 2, q4 = lane & 3;
  const int mwarp = (wid >> 1) * 32, nwarp = (wid & 1) * 32;

  const int aRow = (lane & 7) + (lane & 8);
  const int aCol = (lane & 16) ? 8 : 0;
  const int bRow = (lane & 7) + ((lane & 16) ? 8 : 0);
  const int bCol = (lane & 8) ? 8 : 0;

  auto issue = [&](int kc) {
    char* st = smem + (kc & 1) * PSTG;
#pragma unroll
    for (int l = 0; l < 2; l++) {
      int idx = tid + l * 128, m = idx >> 2, c = idx & 3;
      size_t src = (size_t)(m0 + m) * DMODEL + kc * 32 + c * 8;
      cp16(st + m * 80 + c * 16, Ahs + src);
      cp16(st + PSUB + m * 80 + c * 16, Als + src);
    }
#pragma unroll
    for (int l = 0; l < 2; l++) {
      int idx = tid + l * 128, n = idx >> 2, c = idx & 3;
      size_t src = (size_t)(nb + n) * DMODEL + kc * 32 + c * 8;
      cp16(st + 2 * PSUB + n * 80 + c * 16, g_Wth + src);
      cp16(st + 3 * PSUB + n * 80 + c * 16, g_Wtl + src);
    }
    CP_COMMIT();
  };

  issue(0);
  issue(1);

  float dot[2][4][4] = {};
  const int NKC = DMODEL / 32;  // 64

  for (int kc = 0; kc < NKC; kc++) {
    if (kc + 1 < NKC) { CP_WAIT(1); } else { CP_WAIT(0); }
    __syncthreads();
    const char* st = smem + (kc & 1) * PSTG;
    const __nv_bfloat16* Ah = (const __nv_bfloat16*)st;
    const __nv_bfloat16* Al = (const __nv_bfloat16*)(st + PSUB);
    const __nv_bfloat16* Bh = (const __nv_bfloat16*)(st + 2 * PSUB);
    const __nv_bfloat16* Bl = (const __nv_bfloat16*)(st + 3 * PSUB);

#pragma unroll
    for (int ks = 0; ks < 2; ks++) {
      uint32_t ah[2][4], al[2][4];
#pragma unroll
      for (int mf = 0; mf < 2; mf++) {
        ldmx4(ah[mf], Ah + (mwarp + mf * 16 + aRow) * PSP + ks * 16 + aCol);
        ldmx4(al[mf], Al + (mwarp + mf * 16 + aRow) * PSP + ks * 16 + aCol);
      }
#pragma unroll
      for (int p = 0; p < 2; p++) {
        uint32_t bh[4], bl[4];
        ldmx4(bh, Bh + (nwarp + p * 16 + bRow) * PSP + ks * 16 + bCol);
        ldmx4(bl, Bl + (nwarp + p * 16 + bRow) * PSP + ks * 16 + bCol);
#pragma unroll
        for (int mf = 0; mf < 2; mf++) {
          mma_bf16(dot[mf][2 * p], ah[mf], bh[0], bh[1]);
          mma_bf16(dot[mf][2 * p], ah[mf], bl[0], bl[1]);
          mma_bf16(dot[mf][2 * p], al[mf], bh[0], bh[1]);
          mma_bf16(dot[mf][2 * p + 1], ah[mf], bh[2], bh[3]);
          mma_bf16(dot[mf][2 * p + 1], ah[mf], bl[2], bl[3]);
          mma_bf16(dot[mf][2 * p + 1], al[mf], bh[2], bh[3]);
        }
      }
    }
    __syncthreads();
    if (kc + 2 < NKC) issue(kc + 2);
  }

  // epilogue: split to hi/lo bf16 and write
#pragma unroll
  for (int mf = 0; mf < 2; mf++) {
#pragma unroll
    for (int nf = 0; nf < 4; nf++) {
      int grow = m0 + mwarp + mf * 16 + g;
      __nv_bfloat16 h0, l0, h1, l1;
      if (isQ) {
        int ncol = nb + nwarp + nf * 8 + q4 * 2;  // global Wq col (0..255)
        int head = ncol >> 6, hcol = ncol & 63;
        __nv_bfloat16* Oh = g_qIh + ((size_t)head * ROWS + grow) * 64 + hcol;
        __nv_bfloat16* Ol = g_qIl + ((size_t)head * ROWS + grow) * 64 + hcol;
        split1(dot[mf][nf][0], h0, l0);
        split1(dot[mf][nf][1], h1, l1);
        *(uint32_t*)Oh = pack2(h0, h1);
        *(uint32_t*)Ol = pack2(l0, l1);
        split1(dot[mf][nf][2], h0, l0);
        split1(dot[mf][nf][3], h1, l1);
        *(uint32_t*)(Oh + 8 * 64) = pack2(h0, h1);
        *(uint32_t*)(Ol + 8 * 64) = pack2(l0, l1);
      } else {
        int ncol = nwarp + nf * 8 + q4 * 2;
        __nv_bfloat16* Oh = g_kIh + (size_t)grow * 64 + ncol;
        __nv_bfloat16* Ol = g_kIl + (size_t)grow * 64 + ncol;
        split1(dot[mf][nf][0], h0, l0);
        split1(dot[mf][nf][1], h1, l1);
        *(uint32_t*)Oh = pack2(h0, h1);
        *(uint32_t*)Ol = pack2(l0, l1);
        split1(dot[mf][nf][2], h0, l0);
        split1(dot[mf][nf][3], h1, l1);
        *(uint32_t*)(Oh + 8 * 64) = pack2(h0, h1);
        *(uint32_t*)(Ol + 8 * 64) = pack2(l0, l1);
      }
    }
  }
}

// ---------------------------------------------------------------------------
// Main: CTA 128q x 64k, 8 warps (4x2), warp 32x32, 2 CTAs/SM.
// A (q head) hi/lo double-buffered cp.async; B (k) fixed; per head:
// dot (bf16x3) -> relu -> w-weighted accumulate.
// ---------------------------------------------------------------------------
#define MSP 72
#define MAB (128 * MSP * 2)                 // 18432
#define MBB (64 * MSP * 2)                  // 9216
#define M_B (4 * MAB)
#define M_WS (4 * MAB + 2 * MBB)
#define MAIN_SMEM (4 * MAB + 2 * MBB + 2048)  // 94208

__global__ __launch_bounds__(256, 2) void main_mma_kernel(
    const float* __restrict__ wI, float* __restrict__ out) {
  extern __shared__ __align__(16) char smem[];
  float* ws = (float*)(smem + M_WS);

  const int tid = threadIdx.x, wid = tid >> 5, lane = tid & 31;
  const int g = lane >> 2, q4 = lane & 3;
  const int mwarp = (wid >> 1) * 32, nwarp = (wid & 1) * 32;
  const int b = blockIdx.z, q0 = blockIdx.y * 128, k0 = blockIdx.x * 64;

  const int aRow = (lane & 7) + (lane & 8);
  const int aCol = (lane & 16) ? 8 : 0;
  const int bRow = (lane & 7) + ((lane & 16) ? 8 : 0);
  const int bCol = (lane & 8) ? 8 : 0;

  auto issueA = [&](int h) {
    char* st = smem + (h & 1) * 2 * MAB;
    size_t base = ((size_t)h * ROWS + b * TQDIM + q0) * 64;
#pragma unroll
    for (int l = 0; l < 4; l++) {
      int idx = tid + l * 256, m = idx >> 3, c = idx & 7;
      cp16(st + m * 144 + c * 16, g_qIh + base + (size_t)m * 64 + c * 8);
      cp16(st + MAB + m * 144 + c * 16, g_qIl + base + (size_t)m * 64 + c * 8);
    }
  };

  // prologue: group0 = B + A(0); group1 = A(1)
  {
    char* st = smem + M_B;
    size_t base = ((size_t)b * TKDIM + k0) * 64;
#pragma unroll
    for (int l = 0; l < 2; l++) {
      int idx = tid + l * 256, m = idx >> 3, c = idx & 7;
      cp16(st + m * 144 + c * 16, g_kIh + base + (size_t)m * 64 + c * 8);
      cp16(st + MBB + m * 144 + c * 16, g_kIl + base + (size_t)m * 64 + c * 8);
    }
  }
  issueA(0);
  CP_COMMIT();
  issueA(1);
  CP_COMMIT();
  if (tid < 128)
    *(float4*)&ws[tid * 4] =
        *(const float4*)&wI[(size_t)(b * TQDIM + q0 + tid) * 4];

  const __nv_bfloat16* Bh = (const __nv_bfloat16*)(smem + M_B);
  const __nv_bfloat16* Bl = (const __nv_bfloat16*)(smem + M_B + MBB);

  float acc[2][4][4] = {};

  for (int h = 0; h < NHEADS; h++) {
    if (h + 1 < NHEADS) { CP_WAIT(1); } else { CP_WAIT(0); }
    __syncthreads();
    const __nv_bfloat16* Ah = (const __nv_bfloat16*)(smem + (h & 1) * 2 * MAB);
    const __nv_bfloat16* Al = (const __nv_bfloat16*)((const char*)Ah + MAB);

    float dot[2][4][4] = {};
#pragma unroll
    for (int ks = 0; ks < 4; ks++) {
      uint32_t ah[2][4], al[2][4];
#pragma unroll
      for (int mf = 0; mf < 2; mf++) {
        ldmx4(ah[mf], Ah + (mwarp + mf * 16 + aRow) * MSP + ks * 16 + aCol);
        ldmx4(al[mf], Al + (mwarp + mf * 16 + aRow) * MSP + ks * 16 + aCol);
      }
#pragma unroll
      for (int p = 0; p < 2; p++) {
        uint32_t bh[4], bl[4];
        ldmx4(bh, Bh + (nwarp + p * 16 + bRow) * MSP + ks * 16 + bCol);
        ldmx4(bl, Bl + (nwarp + p * 16 + bRow) * MSP + ks * 16 + bCol);
#pragma unroll
        for (int mf = 0; mf < 2; mf++) {
          mma_bf16(dot[mf][2 * p], ah[mf], bh[0], bh[1]);
          mma_bf16(dot[mf][2 * p], ah[mf], bl[0], bl[1]);
          mma_bf16(dot[mf][2 * p], al[mf], bh[0], bh[1]);
          mma_bf16(dot[mf][2 * p + 1], ah[mf], bh[2], bh[3]);
          mma_bf16(dot[mf][2 * p + 1], ah[mf], bl[2], bl[3]);
          mma_bf16(dot[mf][2 * p + 1], al[mf], bh[2], bh[3]);
        }
      }
    }
    // relu + weighted accumulate
#pragma unroll
    for (int mf = 0; mf < 2; mf++) {
      float wa = ws[(mwarp + mf * 16 + g) * 4 + h];
      float wb = ws[(mwarp + mf * 16 + g + 8) * 4 + h];
#pragma unroll
      for (int nf = 0; nf < 4; nf++) {
        acc[mf][nf][0] = fmaf(wa, fmaxf(dot[mf][nf][0], 0.f), acc[mf][nf][0]);
        acc[mf][nf][1] = fmaf(wa, fmaxf(dot[mf][nf][1], 0.f), acc[mf][nf][1]);
        acc[mf][nf][2] = fmaf(wb, fmaxf(dot[mf][nf][2], 0.f), acc[mf][nf][2]);
        acc[mf][nf][3] = fmaf(wb, fmaxf(dot[mf][nf][3], 0.f), acc[mf][nf][3]);
      }
    }
    if (h + 2 < NHEADS) {
      __syncthreads();  // all warps done with buf (h&1)
      issueA(h + 2);
      CP_COMMIT();
    }
  }

  float* obase = out + (size_t)(b * TQDIM + q0) * TKDIM + k0;
#pragma unroll
  for (int mf = 0; mf < 2; mf++) {
    int r0 = mwarp + mf * 16 + g;
#pragma unroll
    for (int nf = 0; nf < 4; nf++) {
      int col = nwarp + nf * 8 + q4 * 2;
      *(float2*)&obase[(size_t)r0 * TKDIM + col] =
          make_float2(acc[mf][nf][0], acc[mf][nf][1]);
      *(float2*)&obase[(size_t)(r0 + 8) * TKDIM + col] =
          make_float2(acc[mf][nf][2], acc[mf][nf][3]);
    }
  }
}

// ---------------------------------------------------------------------------
extern "C" void kernel_launch(void* const* d_in, const int* in_sizes, int n_in,
                              void* d_out, int out_size) {
  const float* x_q = (const float*)d_in[0];
  const float* x_k = (const float*)d_in[1];
  const float* Wq = (const float*)d_in[2];
  const float* Ww = (const float*)d_in[3];
  const float* Wk = (const float*)d_in[4];
  float* out = (float*)d_out;

  __nv_bfloat16 *xqh, *xql, *xkh, *xkl, *Wth, *Wtl;
  float* wI;
  cudaGetSymbolAddress((void**)&xqh, g_xqh);
  cudaGetSymbolAddress((void**)&xql, g_xql);
  cudaGetSymbolAddress((void**)&xkh, g_xkh);
  cudaGetSymbolAddress((void**)&xkl, g_xkl);
  cudaGetSymbolAddress((void**)&Wth, g_Wth);
  cudaGetSymbolAddress((void**)&Wtl, g_Wtl);
  cudaGetSymbolAddress((void**)&wI, g_wI);

  cudaFuncSetAttribute(proj_kernel, cudaFuncAttributeMaxDynamicSharedMemorySize,
                       PROJ_SMEM);
  cudaFuncSetAttribute(main_mma_kernel,
                       cudaFuncAttributeMaxDynamicSharedMemorySize, MAIN_SMEM);

  const int n4 = ROWS * DMODEL / 4;
  convq_kernel<<<ROWS / 8, 256>>>(x_q, Ww, xqh, xql, wI);
  convert_kernel<<<n4 / 256, 256>>>(x_k, xkh, xkl, n4);
  wt_kernel<<<dim3(DMODEL / 256, 320), 256>>>(Wq, Wk, Wth, Wtl);
  proj_kernel<<<640, 128, PROJ_SMEM>>>();
  main_mma_kernel<<<dim3(TKDIM / 64, TQDIM / 128, 2), 256, MAIN_SMEM>>>(wI,
                                                                        out);
}

// round 11
// speedup vs baseline: 1.1028x; 1.0737x over previous
#include <cuda_runtime.h>
#include <cuda_bf16.h>
#include <cstdint>

// Shapes (fixed)
#define TQDIM 4096
#define TKDIM 4096
#define DMODEL 2048
#define NHEADS 4
#define ROWS 8192  // B*T

// Pre-split inputs (hi/lo bf16)
__device__ __nv_bfloat16 g_xqh[ROWS * DMODEL];
__device__ __nv_bfloat16 g_xql[ROWS * DMODEL];
__device__ __nv_bfloat16 g_xkh[ROWS * DMODEL];
__device__ __nv_bfloat16 g_xkl[ROWS * DMODEL];
__device__ __nv_bfloat16 g_Wth[320 * DMODEL];  // [n][k]; n<256: Wq col, n>=256: Wk col
__device__ __nv_bfloat16 g_Wtl[320 * DMODEL];
// Projection outputs (hi/lo bf16); q head-major [h][row][64]
__device__ __nv_bfloat16 g_qIh[NHEADS * ROWS * 64];
__device__ __nv_bfloat16 g_qIl[NHEADS * ROWS * 64];
__device__ __nv_bfloat16 g_kIh[ROWS * 64];
__device__ __nv_bfloat16 g_kIl[ROWS * 64];
__device__ float g_wI[ROWS * 4];

// ---------------------------------------------------------------------------
// helpers
// ---------------------------------------------------------------------------
__device__ __forceinline__ void split1(float v, __nv_bfloat16& h,
                                       __nv_bfloat16& l) {
  h = __float2bfloat16(v);
  l = __float2bfloat16(v - __bfloat162float(h));
}
__device__ __forceinline__ uint32_t pack2(__nv_bfloat16 a, __nv_bfloat16 b) {
  return (uint32_t)__bfloat16_as_ushort(a) |
         ((uint32_t)__bfloat16_as_ushort(b) << 16);
}
__device__ __forceinline__ void split_f4(float4 v, uint2& hi, uint2& lo) {
  __nv_bfloat16 h0, l0, h1, l1, h2, l2, h3, l3;
  split1(v.x, h0, l0); split1(v.y, h1, l1);
  split1(v.z, h2, l2); split1(v.w, h3, l3);
  hi.x = pack2(h0, h1); hi.y = pack2(h2, h3);
  lo.x = pack2(l0, l1); lo.y = pack2(l2, l3);
}

__device__ __forceinline__ void mma_bf16(float* c, const uint32_t* a,
                                         uint32_t b0, uint32_t b1) {
  asm volatile(
      "mma.sync.aligned.m16n8k16.row.col.f32.bf16.bf16.f32 "
      "{%0,%1,%2,%3}, {%4,%5,%6,%7}, {%8,%9}, {%0,%1,%2,%3};\n"
      : "+f"(c[0]), "+f"(c[1]), "+f"(c[2]), "+f"(c[3])
      : "r"(a[0]), "r"(a[1]), "r"(a[2]), "r"(a[3]), "r"(b0), "r"(b1));
}

__device__ __forceinline__ void ldmx4(uint32_t* r, const void* p) {
  uint32_t a = (uint32_t)__cvta_generic_to_shared(p);
  asm volatile(
      "ldmatrix.sync.aligned.m8n8.x4.shared.b16 {%0,%1,%2,%3}, [%4];"
      : "=r"(r[0]), "=r"(r[1]), "=r"(r[2]), "=r"(r[3])
      : "r"(a));
}

__device__ __forceinline__ void cp16(void* dst, const void* src) {
  uint32_t d = (uint32_t)__cvta_generic_to_shared(dst);
  asm volatile("cp.async.cg.shared.global [%0], [%1], 16;" :: "r"(d), "l"(src));
}
#define CP_COMMIT() asm volatile("cp.async.commit_group;" ::: "memory")
#define CP_WAIT(n) asm volatile("cp.async.wait_group %0;" :: "n"(n) : "memory")

// ---------------------------------------------------------------------------
// Merged prep: [0,1024) convq+wI | [1024,17408) convert x_k | [17408,19968) wt
// ---------------------------------------------------------------------------
__global__ __launch_bounds__(256) void prep_kernel(
    const float* __restrict__ x_q, const float* __restrict__ x_k,
    const float* __restrict__ Wq, const float* __restrict__ Ww,
    const float* __restrict__ Wk) {
  const int bx = blockIdx.x;
  const int tid = threadIdx.x;
  if (bx < 1024) {
    // convq: hi/lo split of x_q fused with w_I = x_q @ Ww; one warp per row
    int row = bx * 8 + (tid >> 5);
    int lane = tid & 31;
    const float4* xr = (const float4*)(x_q + (size_t)row * DMODEL);
    uint2* oh = (uint2*)(g_xqh + (size_t)row * DMODEL);
    uint2* ol = (uint2*)(g_xql + (size_t)row * DMODEL);
    float a0 = 0.f, a1 = 0.f, a2 = 0.f, a3 = 0.f;
#pragma unroll
    for (int i = 0; i < 16; i++) {
      int d4 = lane + i * 32;
      float4 v = xr[d4];
      uint2 hi, lo;
      split_f4(v, hi, lo);
      oh[d4] = hi;
      ol[d4] = lo;
      int d = d4 * 4;
      float4 w;
      w = *(const float4*)&Ww[(d + 0) * 4];
      a0 = fmaf(v.x, w.x, a0); a1 = fmaf(v.x, w.y, a1);
      a2 = fmaf(v.x, w.z, a2); a3 = fmaf(v.x, w.w, a3);
      w = *(const float4*)&Ww[(d + 1) * 4];
      a0 = fmaf(v.y, w.x, a0); a1 = fmaf(v.y, w.y, a1);
      a2 = fmaf(v.y, w.z, a2); a3 = fmaf(v.y, w.w, a3);
      w = *(const float4*)&Ww[(d + 2) * 4];
      a0 = fmaf(v.z, w.x, a0); a1 = fmaf(v.z, w.y, a1);
      a2 = fmaf(v.z, w.z, a2); a3 = fmaf(v.z, w.w, a3);
      w = *(const float4*)&Ww[(d + 3) * 4];
      a0 = fmaf(v.w, w.x, a0); a1 = fmaf(v.w, w.y, a1);
      a2 = fmaf(v.w, w.z, a2); a3 = fmaf(v.w, w.w, a3);
    }
#pragma unroll
    for (int off = 16; off; off >>= 1) {
      a0 += __shfl_down_sync(0xffffffffu, a0, off);
      a1 += __shfl_down_sync(0xffffffffu, a1, off);
      a2 += __shfl_down_sync(0xffffffffu, a2, off);
      a3 += __shfl_down_sync(0xffffffffu, a3, off);
    }
    if (lane == 0)
      *(float4*)&g_wI[(size_t)row * 4] = make_float4(a0, a1, a2, a3);
  } else if (bx < 17408) {
    // convert x_k
    int i = (bx - 1024) * 256 + tid;  // < ROWS*DMODEL/4
    float4 v = ((const float4*)x_k)[i];
    uint2 hi, lo;
    split_f4(v, hi, lo);
    ((uint2*)g_xkh)[i] = hi;
    ((uint2*)g_xkl)[i] = lo;
  } else {
    // wt: Wt[n][k] = W[k][n], hi/lo
    int idx = bx - 17408;       // 0..2559
    int n = idx >> 3;           // 0..319
    int k = (idx & 7) * 256 + tid;
    float v =
        (n < 256) ? Wq[(size_t)k * 256 + n] : Wk[(size_t)k * 64 + (n - 256)];
    __nv_bfloat16 h, l;
    split1(v, h, l);
    g_Wth[(size_t)n * DMODEL + k] = h;
    g_Wtl[(size_t)n * DMODEL + k] = l;
  }
}

// ---------------------------------------------------------------------------
// Projection: C = A @ Wt^T (pre-split bf16), bf16x3 HMMA.
// CTA 64 x 64, 4 warps (2x2 of 32x32), K-chunk 32, 2-stage cp.async,
// 4 CTAs/SM. Grid 640:
//  blocks 0..511: q (m0=(bx>>2)*64, nb=(bx&3)*64); 512..639: k (nb=256).
// ---------------------------------------------------------------------------
#define PSP 40                    // halves stride (80 B rows)
#define PSUB (64 * 80)            // 5120 B per subtile
#define PSTG (4 * PSUB)           // 20480: Ah, Al, Bh, Bl
#define PROJ_SMEM (2 * PSTG)      // 40960

__global__ __launch_bounds__(128, 4) void proj_kernel() {
  extern __shared__ __align__(16) char smem[];
  const int bx = blockIdx.x;
  const bool isQ = bx < 512;
  const int m0 = isQ ? (bx >> 2) * 64 : (bx - 512) * 64;
  const int nb = isQ ? (bx & 3) * 64 : 256;  // Wt row base

  const __nv_bfloat16* Ahs = isQ ? g_xqh : g_xkh;
  const __nv_bfloat16* Als = isQ ? g_xql : g_xkl;

  const int tid = threadIdx.x, wid = tid >> 5, lane = tid & 31;
  const int g = lane >> 2, q4 = lane & 3;
  const int mwarp = (wid >> 1) * 32, nwarp = (wid & 1) * 32;

  const int aRow = (lane & 7) + (lane & 8);
  const int aCol = (lane & 16) ? 8 : 0;
  const int bRow = (lane & 7) + ((lane & 16) ? 8 : 0);
  const int bCol = (lane & 8) ? 8 : 0;

  auto issue = [&](int kc) {
    char* st = smem + (kc & 1) * PSTG;
#pragma unroll
    for (int l = 0; l < 2; l++) {
      int idx = tid + l * 128, m = idx >> 2, c = idx & 3;
      size_t src = (size_t)(m0 + m) * DMODEL + kc * 32 + c * 8;
      cp16(st + m * 80 + c * 16, Ahs + src);
      cp16(st + PSUB + m * 80 + c * 16, Als + src);
    }
#pragma unroll
    for (int l = 0; l < 2; l++) {
      int idx = tid + l * 128, n = idx >> 2, c = idx & 3;
      size_t src = (size_t)(nb + n) * DMODEL + kc * 32 + c * 8;
      cp16(st + 2 * PSUB + n * 80 + c * 16, g_Wth + src);
      cp16(st + 3 * PSUB + n * 80 + c * 16, g_Wtl + src);
    }
    CP_COMMIT();
  };

  issue(0);
  issue(1);

  float dot[2][4][4] = {};
  const int NKC = DMODEL / 32;  // 64

  for (int kc = 0; kc < NKC; kc++) {
    if (kc + 1 < NKC) { CP_WAIT(1); } else { CP_WAIT(0); }
    __syncthreads();
    const char* st = smem + (kc & 1) * PSTG;
    const __nv_bfloat16* Ah = (const __nv_bfloat16*)st;
    const __nv_bfloat16* Al = (const __nv_bfloat16*)(st + PSUB);
    const __nv_bfloat16* Bh = (const __nv_bfloat16*)(st + 2 * PSUB);
    const __nv_bfloat16* Bl = (const __nv_bfloat16*)(st + 3 * PSUB);

#pragma unroll
    for (int ks = 0; ks < 2; ks++) {
      uint32_t ah[2][4], al[2][4];
#pragma unroll
      for (int mf = 0; mf < 2; mf++) {
        ldmx4(ah[mf], Ah + (mwarp + mf * 16 + aRow) * PSP + ks * 16 + aCol);
        ldmx4(al[mf], Al + (mwarp + mf * 16 + aRow) * PSP + ks * 16 + aCol);
      }
#pragma unroll
      for (int p = 0; p < 2; p++) {
        uint32_t bh[4], bl[4];
        ldmx4(bh, Bh + (nwarp + p * 16 + bRow) * PSP + ks * 16 + bCol);
        ldmx4(bl, Bl + (nwarp + p * 16 + bRow) * PSP + ks * 16 + bCol);
#pragma unroll
        for (int mf = 0; mf < 2; mf++) {
          mma_bf16(dot[mf][2 * p], ah[mf], bh[0], bh[1]);
          mma_bf16(dot[mf][2 * p], ah[mf], bl[0], bl[1]);
          mma_bf16(dot[mf][2 * p], al[mf], bh[0], bh[1]);
          mma_bf16(dot[mf][2 * p + 1], ah[mf], bh[2], bh[3]);
          mma_bf16(dot[mf][2 * p + 1], ah[mf], bl[2], bl[3]);
          mma_bf16(dot[mf][2 * p + 1], al[mf], bh[2], bh[3]);
        }
      }
    }
    __syncthreads();
    if (kc + 2 < NKC) issue(kc + 2);
  }

  // epilogue: split to hi/lo bf16 and write
#pragma unroll
  for (int mf = 0; mf < 2; mf++) {
#pragma unroll
    for (int nf = 0; nf < 4; nf++) {
      int grow = m0 + mwarp + mf * 16 + g;
      __nv_bfloat16 h0, l0, h1, l1;
      if (isQ) {
        int ncol = nb + nwarp + nf * 8 + q4 * 2;  // global Wq col (0..255)
        int head = ncol >> 6, hcol = ncol & 63;
        __nv_bfloat16* Oh = g_qIh + ((size_t)head * ROWS + grow) * 64 + hcol;
        __nv_bfloat16* Ol = g_qIl + ((size_t)head * ROWS + grow) * 64 + hcol;
        split1(dot[mf][nf][0], h0, l0);
        split1(dot[mf][nf][1], h1, l1);
        *(uint32_t*)Oh = pack2(h0, h1);
        *(uint32_t*)Ol = pack2(l0, l1);
        split1(dot[mf][nf][2], h0, l0);
        split1(dot[mf][nf][3], h1, l1);
        *(uint32_t*)(Oh + 8 * 64) = pack2(h0, h1);
        *(uint32_t*)(Ol + 8 * 64) = pack2(l0, l1);
      } else {
        int ncol = nwarp + nf * 8 + q4 * 2;
        __nv_bfloat16* Oh = g_kIh + (size_t)grow * 64 + ncol;
        __nv_bfloat16* Ol = g_kIl + (size_t)grow * 64 + ncol;
        split1(dot[mf][nf][0], h0, l0);
        split1(dot[mf][nf][1], h1, l1);
        *(uint32_t*)Oh = pack2(h0, h1);
        *(uint32_t*)Ol = pack2(l0, l1);
        split1(dot[mf][nf][2], h0, l0);
        split1(dot[mf][nf][3], h1, l1);
        *(uint32_t*)(Oh + 8 * 64) = pack2(h0, h1);
        *(uint32_t*)(Ol + 8 * 64) = pack2(l0, l1);
      }
    }
  }
}

// ---------------------------------------------------------------------------
// Main: CTA 64q x 64k, 128 threads (4 warps, 2x2 of 32x32), 4 CTAs/SM.
// A (q head) hi/lo double-buffered cp.async; B (k) fixed; per head:
// dot (bf16x3) -> relu -> w-weighted accumulate.
// ---------------------------------------------------------------------------
#define MSP 72
#define MAB (64 * MSP * 2)                  // 9216
#define M_B (4 * MAB)                       // B hi at 4*MAB, lo at 5*MAB
#define M_WS (6 * MAB)
#define MAIN_SMEM (6 * MAB + 1024)          // 56320

__global__ __launch_bounds__(128, 4) void main_mma_kernel(
    const float* __restrict__ wI, float* __restrict__ out) {
  extern __shared__ __align__(16) char smem[];
  float* ws = (float*)(smem + M_WS);

  const int tid = threadIdx.x, wid = tid >> 5, lane = tid & 31;
  const int g = lane >> 2, q4 = lane & 3;
  const int mwarp = (wid >> 1) * 32, nwarp = (wid & 1) * 32;
  const int b = blockIdx.z, q0 = blockIdx.y * 64, k0 = blockIdx.x * 64;

  const int aRow = (lane & 7) + (lane & 8);
  const int aCol = (lane & 16) ? 8 : 0;
  const int bRow = (lane & 7) + ((lane & 16) ? 8 : 0);
  const int bCol = (lane & 8) ? 8 : 0;

  auto issueA = [&](int h) {
    char* st = smem + (h & 1) * 2 * MAB;
    size_t base = ((size_t)h * ROWS + b * TQDIM + q0) * 64;
#pragma unroll
    for (int l = 0; l < 4; l++) {
      int idx = tid + l * 128, m = idx >> 3, c = idx & 7;
      cp16(st + m * 144 + c * 16, g_qIh + base + (size_t)m * 64 + c * 8);
      cp16(st + MAB + m * 144 + c * 16, g_qIl + base + (size_t)m * 64 + c * 8);
    }
  };

  // prologue: group0 = B + A(0); group1 = A(1)
  {
    char* st = smem + M_B;
    size_t base = ((size_t)b * TKDIM + k0) * 64;
#pragma unroll
    for (int l = 0; l < 4; l++) {
      int idx = tid + l * 128, m = idx >> 3, c = idx & 7;
      cp16(st + m * 144 + c * 16, g_kIh + base + (size_t)m * 64 + c * 8);
      cp16(st + MAB + m * 144 + c * 16, g_kIl + base + (size_t)m * 64 + c * 8);
    }
  }
  issueA(0);
  CP_COMMIT();
  issueA(1);
  CP_COMMIT();
  if (tid < 64)
    *(float4*)&ws[tid * 4] =
        *(const float4*)&wI[(size_t)(b * TQDIM + q0 + tid) * 4];

  const __nv_bfloat16* Bh = (const __nv_bfloat16*)(smem + M_B);
  const __nv_bfloat16* Bl = (const __nv_bfloat16*)(smem + M_B + MAB);

  float acc[2][4][4] = {};

  for (int h = 0; h < NHEADS; h++) {
    if (h + 1 < NHEADS) { CP_WAIT(1); } else { CP_WAIT(0); }
    __syncthreads();
    const __nv_bfloat16* Ah = (const __nv_bfloat16*)(smem + (h & 1) * 2 * MAB);
    const __nv_bfloat16* Al = (const __nv_bfloat16*)((const char*)Ah + MAB);

    float dot[2][4][4] = {};
#pragma unroll
    for (int ks = 0; ks < 4; ks++) {
      uint32_t ah[2][4], al[2][4];
#pragma unroll
      for (int mf = 0; mf < 2; mf++) {
        ldmx4(ah[mf], Ah + (mwarp + mf * 16 + aRow) * MSP + ks * 16 + aCol);
        ldmx4(al[mf], Al + (mwarp + mf * 16 + aRow) * MSP + ks * 16 + aCol);
      }
#pragma unroll
      for (int p = 0; p < 2; p++) {
        uint32_t bh[4], bl[4];
        ldmx4(bh, Bh + (nwarp + p * 16 + bRow) * MSP + ks * 16 + bCol);
        ldmx4(bl, Bl + (nwarp + p * 16 + bRow) * MSP + ks * 16 + bCol);
#pragma unroll
        for (int mf = 0; mf < 2; mf++) {
          mma_bf16(dot[mf][2 * p], ah[mf], bh[0], bh[1]);
          mma_bf16(dot[mf][2 * p], ah[mf], bl[0], bl[1]);
          mma_bf16(dot[mf][2 * p], al[mf], bh[0], bh[1]);
          mma_bf16(dot[mf][2 * p + 1], ah[mf], bh[2], bh[3]);
          mma_bf16(dot[mf][2 * p + 1], ah[mf], bl[2], bl[3]);
          mma_bf16(dot[mf][2 * p + 1], al[mf], bh[2], bh[3]);
        }
      }
    }
    // relu + weighted accumulate
#pragma unroll
    for (int mf = 0; mf < 2; mf++) {
      float wa = ws[(mwarp + mf * 16 + g) * 4 + h];
      float wb = ws[(mwarp + mf * 16 + g + 8) * 4 + h];
#pragma unroll
      for (int nf = 0; nf < 4; nf++) {
        acc[mf][nf][0] = fmaf(wa, fmaxf(dot[mf][nf][0], 0.f), acc[mf][nf][0]);
        acc[mf][nf][1] = fmaf(wa, fmaxf(dot[mf][nf][1], 0.f), acc[mf][nf][1]);
        acc[mf][nf][2] = fmaf(wb, fmaxf(dot[mf][nf][2], 0.f), acc[mf][nf][2]);
        acc[mf][nf][3] = fmaf(wb, fmaxf(dot[mf][nf][3], 0.f), acc[mf][nf][3]);
      }
    }
    if (h + 2 < NHEADS) {
      __syncthreads();  // all warps done with buf (h&1)
      issueA(h + 2);
      CP_COMMIT();
    }
  }

  float* obase = out + (size_t)(b * TQDIM + q0) * TKDIM + k0;
#pragma unroll
  for (int mf = 0; mf < 2; mf++) {
    int r0 = mwarp + mf * 16 + g;
#pragma unroll
    for (int nf = 0; nf < 4; nf++) {
      int col = nwarp + nf * 8 + q4 * 2;
      *(float2*)&obase[(size_t)r0 * TKDIM + col] =
          make_float2(acc[mf][nf][0], acc[mf][nf][1]);
      *(float2*)&obase[(size_t)(r0 + 8) * TKDIM + col] =
          make_float2(acc[mf][nf][2], acc[mf][nf][3]);
    }
  }
}

// ---------------------------------------------------------------------------
extern "C" void kernel_launch(void* const* d_in, const int* in_sizes, int n_in,
                              void* d_out, int out_size) {
  const float* x_q = (const float*)d_in[0];
  const float* x_k = (const float*)d_in[1];
  const float* Wq = (const float*)d_in[2];
  const float* Ww = (const float*)d_in[3];
  const float* Wk = (const float*)d_in[4];
  float* out = (float*)d_out;

  float* wI;
  cudaGetSymbolAddress((void**)&wI, g_wI);

  cudaFuncSetAttribute(proj_kernel, cudaFuncAttributeMaxDynamicSharedMemorySize,
                       PROJ_SMEM);
  cudaFuncSetAttribute(main_mma_kernel,
                       cudaFuncAttributeMaxDynamicSharedMemorySize, MAIN_SMEM);

  prep_kernel<<<19968, 256>>>(x_q, x_k, Wq, Ww, Wk);
  proj_kernel<<<640, 128, PROJ_SMEM>>>();
  main_mma_kernel<<<dim3(TKDIM / 64, TQDIM / 64, 2), 128, MAIN_SMEM>>>(wI,
                                                                       out);
}

// round 12
// speedup vs baseline: 1.1331x; 1.0275x over previous
#include <cuda_runtime.h>
#include <cuda_bf16.h>
#include <cstdint>

// Shapes (fixed)
#define TQDIM 4096
#define TKDIM 4096
#define DMODEL 2048
#define NHEADS 4
#define ROWS 8192  // B*T

// Pre-split inputs (hi/lo bf16)
__device__ __nv_bfloat16 g_xqh[ROWS * DMODEL];
__device__ __nv_bfloat16 g_xql[ROWS * DMODEL];
__device__ __nv_bfloat16 g_xkh[ROWS * DMODEL];
__device__ __nv_bfloat16 g_xkl[ROWS * DMODEL];
__device__ __nv_bfloat16 g_Wth[320 * DMODEL];  // [n][k]; n<256: Wq col, n>=256: Wk col
__device__ __nv_bfloat16 g_Wtl[320 * DMODEL];
// Projection outputs (hi/lo bf16); q head-major [h][row][64]
__device__ __nv_bfloat16 g_qIh[NHEADS * ROWS * 64];
__device__ __nv_bfloat16 g_qIl[NHEADS * ROWS * 64];
__device__ __nv_bfloat16 g_kIh[ROWS * 64];
__device__ __nv_bfloat16 g_kIl[ROWS * 64];
__device__ float g_wI[ROWS * 4];

// ---------------------------------------------------------------------------
// helpers
// ---------------------------------------------------------------------------
__device__ __forceinline__ void split1(float v, __nv_bfloat16& h,
                                       __nv_bfloat16& l) {
  h = __float2bfloat16(v);
  l = __float2bfloat16(v - __bfloat162float(h));
}
__device__ __forceinline__ uint32_t pack2(__nv_bfloat16 a, __nv_bfloat16 b) {
  return (uint32_t)__bfloat16_as_ushort(a) |
         ((uint32_t)__bfloat16_as_ushort(b) << 16);
}
// packed float2 -> bf16x2 (lo half = first operand pair's low element)
__device__ __forceinline__ uint32_t cvt2(float lo, float hi) {
  uint32_t r;
  asm("cvt.rn.bf16x2.f32 %0, %1, %2;" : "=r"(r) : "f"(hi), "f"(lo));
  return r;
}
// fast float4 hi/lo split via packed cvt (same rn rounding as split1)
__device__ __forceinline__ void split_f4(float4 v, uint2& hi, uint2& lo) {
  uint32_t h01 = cvt2(v.x, v.y);
  uint32_t h23 = cvt2(v.z, v.w);
  float h0f = __uint_as_float(h01 << 16);
  float h1f = __uint_as_float(h01 & 0xffff0000u);
  float h2f = __uint_as_float(h23 << 16);
  float h3f = __uint_as_float(h23 & 0xffff0000u);
  uint32_t l01 = cvt2(v.x - h0f, v.y - h1f);
  uint32_t l23 = cvt2(v.z - h2f, v.w - h3f);
  hi.x = h01; hi.y = h23;
  lo.x = l01; lo.y = l23;
}

__device__ __forceinline__ void mma_bf16(float* c, const uint32_t* a,
                                         uint32_t b0, uint32_t b1) {
  asm volatile(
      "mma.sync.aligned.m16n8k16.row.col.f32.bf16.bf16.f32 "
      "{%0,%1,%2,%3}, {%4,%5,%6,%7}, {%8,%9}, {%0,%1,%2,%3};\n"
      : "+f"(c[0]), "+f"(c[1]), "+f"(c[2]), "+f"(c[3])
      : "r"(a[0]), "r"(a[1]), "r"(a[2]), "r"(a[3]), "r"(b0), "r"(b1));
}

__device__ __forceinline__ void ldmx4(uint32_t* r, const void* p) {
  uint32_t a = (uint32_t)__cvta_generic_to_shared(p);
  asm volatile(
      "ldmatrix.sync.aligned.m8n8.x4.shared.b16 {%0,%1,%2,%3}, [%4];"
      : "=r"(r[0]), "=r"(r[1]), "=r"(r[2]), "=r"(r[3])
      : "r"(a));
}

__device__ __forceinline__ void cp16(void* dst, const void* src) {
  uint32_t d = (uint32_t)__cvta_generic_to_shared(dst);
  asm volatile("cp.async.cg.shared.global [%0], [%1], 16;" :: "r"(d), "l"(src));
}
#define CP_COMMIT() asm volatile("cp.async.commit_group;" ::: "memory")
#define CP_WAIT(n) asm volatile("cp.async.wait_group %0;" :: "n"(n) : "memory")

// ---------------------------------------------------------------------------
// Merged prep: [0,1024) convq+wI | [1024,17408) convert x_k | [17408,19968) wt
// ---------------------------------------------------------------------------
__global__ __launch_bounds__(256) void prep_kernel(
    const float* __restrict__ x_q, const float* __restrict__ x_k,
    const float* __restrict__ Wq, const float* __restrict__ Ww,
    const float* __restrict__ Wk) {
  const int bx = blockIdx.x;
  const int tid = threadIdx.x;
  if (bx < 1024) {
    // convq: hi/lo split of x_q fused with w_I = x_q @ Ww; one warp per row
    int row = bx * 8 + (tid >> 5);
    int lane = tid & 31;
    const float4* xr = (const float4*)(x_q + (size_t)row * DMODEL);
    uint2* oh = (uint2*)(g_xqh + (size_t)row * DMODEL);
    uint2* ol = (uint2*)(g_xql + (size_t)row * DMODEL);
    float a0 = 0.f, a1 = 0.f, a2 = 0.f, a3 = 0.f;
#pragma unroll
    for (int i = 0; i < 16; i++) {
      int d4 = lane + i * 32;
      float4 v = xr[d4];
      uint2 hi, lo;
      split_f4(v, hi, lo);
      oh[d4] = hi;
      ol[d4] = lo;
      int d = d4 * 4;
      float4 w;
      w = *(const float4*)&Ww[(d + 0) * 4];
      a0 = fmaf(v.x, w.x, a0); a1 = fmaf(v.x, w.y, a1);
      a2 = fmaf(v.x, w.z, a2); a3 = fmaf(v.x, w.w, a3);
      w = *(const float4*)&Ww[(d + 1) * 4];
      a0 = fmaf(v.y, w.x, a0); a1 = fmaf(v.y, w.y, a1);
      a2 = fmaf(v.y, w.z, a2); a3 = fmaf(v.y, w.w, a3);
      w = *(const float4*)&Ww[(d + 2) * 4];
      a0 = fmaf(v.z, w.x, a0); a1 = fmaf(v.z, w.y, a1);
      a2 = fmaf(v.z, w.z, a2); a3 = fmaf(v.z, w.w, a3);
      w = *(const float4*)&Ww[(d + 3) * 4];
      a0 = fmaf(v.w, w.x, a0); a1 = fmaf(v.w, w.y, a1);
      a2 = fmaf(v.w, w.z, a2); a3 = fmaf(v.w, w.w, a3);
    }
#pragma unroll
    for (int off = 16; off; off >>= 1) {
      a0 += __shfl_down_sync(0xffffffffu, a0, off);
      a1 += __shfl_down_sync(0xffffffffu, a1, off);
      a2 += __shfl_down_sync(0xffffffffu, a2, off);
      a3 += __shfl_down_sync(0xffffffffu, a3, off);
    }
    if (lane == 0)
      *(float4*)&g_wI[(size_t)row * 4] = make_float4(a0, a1, a2, a3);
  } else if (bx < 17408) {
    // convert x_k
    int i = (bx - 1024) * 256 + tid;  // < ROWS*DMODEL/4
    float4 v = ((const float4*)x_k)[i];
    uint2 hi, lo;
    split_f4(v, hi, lo);
    ((uint2*)g_xkh)[i] = hi;
    ((uint2*)g_xkl)[i] = lo;
  } else {
    // wt: Wt[n][k] = W[k][n], hi/lo
    int idx = bx - 17408;       // 0..2559
    int n = idx >> 3;           // 0..319
    int k = (idx & 7) * 256 + tid;
    float v =
        (n < 256) ? Wq[(size_t)k * 256 + n] : Wk[(size_t)k * 64 + (n - 256)];
    __nv_bfloat16 h, l;
    split1(v, h, l);
    g_Wth[(size_t)n * DMODEL + k] = h;
    g_Wtl[(size_t)n * DMODEL + k] = l;
  }
}

// ---------------------------------------------------------------------------
// Projection: C = A @ Wt^T (pre-split bf16), bf16x3 HMMA.
// CTA 64 x 64, 4 warps (2x2 of 32x32), K-chunk 32, 3-stage cp.async ring
// (single __syncthreads per chunk; 2-iteration latency lookahead).
// Grid 640: blocks 0..511: q (m0=(bx>>2)*64, nb=(bx&3)*64); 512..639: k.
// ---------------------------------------------------------------------------
#define PSP 40                    // halves stride (80 B rows)
#define PSUB (64 * 80)            // 5120 B per subtile
#define PSTG (4 * PSUB)           // 20480: Ah, Al, Bh, Bl
#define PROJ_SMEM (3 * PSTG)      // 61440

__global__ __launch_bounds__(128, 3) void proj_kernel() {
  extern __shared__ __align__(16) char smem[];
  const int bx = blockIdx.x;
  const bool isQ = bx < 512;
  const int m0 = isQ ? (bx >> 2) * 64 : (bx - 512) * 64;
  const int nb = isQ ? (bx & 3) * 64 : 256;  // Wt row base

  const __nv_bfloat16* Ahs = isQ ? g_xqh : g_xkh;
  const __nv_bfloat16* Als = isQ ? g_xql : g_xkl;

  const int tid = threadIdx.x, wid = tid >> 5, lane = tid & 31;
  const int g = lane >> 2, q4 = lane & 3;
  const int mwarp = (wid >> 1) * 32, nwarp = (wid & 1) * 32;

  const int aRow = (lane & 7) + (lane & 8);
  const int aCol = (lane & 16) ? 8 : 0;
  const int bRow = (lane & 7) + ((lane & 16) ? 8 : 0);
  const int bCol = (lane & 8) ? 8 : 0;

  auto issue = [&](int kc) {
    char* st = smem + (kc % 3) * PSTG;
#pragma unroll
    for (int l = 0; l < 2; l++) {
      int idx = tid + l * 128, m = idx >> 2, c = idx & 3;
      size_t src = (size_t)(m0 + m) * DMODEL + kc * 32 + c * 8;
      cp16(st + m * 80 + c * 16, Ahs + src);
      cp16(st + PSUB + m * 80 + c * 16, Als + src);
    }
#pragma unroll
    for (int l = 0; l < 2; l++) {
      int idx = tid + l * 128, n = idx >> 2, c = idx & 3;
      size_t src = (size_t)(nb + n) * DMODEL + kc * 32 + c * 8;
      cp16(st + 2 * PSUB + n * 80 + c * 16, g_Wth + src);
      cp16(st + 3 * PSUB + n * 80 + c * 16, g_Wtl + src);
    }
    CP_COMMIT();
  };

  issue(0);
  issue(1);

  float dot[2][4][4] = {};
  const int NKC = DMODEL / 32;  // 64

  for (int kc = 0; kc < NKC; kc++) {
    if (kc + 1 < NKC) { CP_WAIT(1); } else { CP_WAIT(0); }
    __syncthreads();  // all warps done with buf (kc-1)%3 == (kc+2)%3
    if (kc + 2 < NKC) issue(kc + 2);

    const char* st = smem + (kc % 3) * PSTG;
    const __nv_bfloat16* Ah = (const __nv_bfloat16*)st;
    const __nv_bfloat16* Al = (const __nv_bfloat16*)(st + PSUB);
    const __nv_bfloat16* Bh = (const __nv_bfloat16*)(st + 2 * PSUB);
    const __nv_bfloat16* Bl = (const __nv_bfloat16*)(st + 3 * PSUB);

#pragma unroll
    for (int ks = 0; ks < 2; ks++) {
      uint32_t ah[2][4], al[2][4];
#pragma unroll
      for (int mf = 0; mf < 2; mf++) {
        ldmx4(ah[mf], Ah + (mwarp + mf * 16 + aRow) * PSP + ks * 16 + aCol);
        ldmx4(al[mf], Al + (mwarp + mf * 16 + aRow) * PSP + ks * 16 + aCol);
      }
#pragma unroll
      for (int p = 0; p < 2; p++) {
        uint32_t bh[4], bl[4];
        ldmx4(bh, Bh + (nwarp + p * 16 + bRow) * PSP + ks * 16 + bCol);
        ldmx4(bl, Bl + (nwarp + p * 16 + bRow) * PSP + ks * 16 + bCol);
#pragma unroll
        for (int mf = 0; mf < 2; mf++) {
          mma_bf16(dot[mf][2 * p], ah[mf], bh[0], bh[1]);
          mma_bf16(dot[mf][2 * p], ah[mf], bl[0], bl[1]);
          mma_bf16(dot[mf][2 * p], al[mf], bh[0], bh[1]);
          mma_bf16(dot[mf][2 * p + 1], ah[mf], bh[2], bh[3]);
          mma_bf16(dot[mf][2 * p + 1], ah[mf], bl[2], bl[3]);
          mma_bf16(dot[mf][2 * p + 1], al[mf], bh[2], bh[3]);
        }
      }
    }
  }

  // epilogue: split to hi/lo bf16 and write
#pragma unroll
  for (int mf = 0; mf < 2; mf++) {
#pragma unroll
    for (int nf = 0; nf < 4; nf++) {
      int grow = m0 + mwarp + mf * 16 + g;
      __nv_bfloat16 h0, l0, h1, l1;
      if (isQ) {
        int ncol = nb + nwarp + nf * 8 + q4 * 2;  // global Wq col (0..255)
        int head = ncol >> 6, hcol = ncol & 63;
        __nv_bfloat16* Oh = g_qIh + ((size_t)head * ROWS + grow) * 64 + hcol;
        __nv_bfloat16* Ol = g_qIl + ((size_t)head * ROWS + grow) * 64 + hcol;
        split1(dot[mf][nf][0], h0, l0);
        split1(dot[mf][nf][1], h1, l1);
        *(uint32_t*)Oh = pack2(h0, h1);
        *(uint32_t*)Ol = pack2(l0, l1);
        split1(dot[mf][nf][2], h0, l0);
        split1(dot[mf][nf][3], h1, l1);
        *(uint32_t*)(Oh + 8 * 64) = pack2(h0, h1);
        *(uint32_t*)(Ol + 8 * 64) = pack2(l0, l1);
      } else {
        int ncol = nwarp + nf * 8 + q4 * 2;
        __nv_bfloat16* Oh = g_kIh + (size_t)grow * 64 + ncol;
        __nv_bfloat16* Ol = g_kIl + (size_t)grow * 64 + ncol;
        split1(dot[mf][nf][0], h0, l0);
        split1(dot[mf][nf][1], h1, l1);
        *(uint32_t*)Oh = pack2(h0, h1);
        *(uint32_t*)Ol = pack2(l0, l1);
        split1(dot[mf][nf][2], h0, l0);
        split1(dot[mf][nf][3], h1, l1);
        *(uint32_t*)(Oh + 8 * 64) = pack2(h0, h1);
        *(uint32_t*)(Ol + 8 * 64) = pack2(l0, l1);
      }
    }
  }
}

// ---------------------------------------------------------------------------
// Main: CTA 64q x 64k, 128 threads (4 warps, 2x2 of 32x32), 4 CTAs/SM.
// A (q head) hi/lo double-buffered cp.async; B (k) fixed; per head:
// dot (bf16x3) -> relu -> w-weighted accumulate.
// ---------------------------------------------------------------------------
#define MSP 72
#define MAB (64 * MSP * 2)                  // 9216
#define M_B (4 * MAB)                       // B hi at 4*MAB, lo at 5*MAB
#define M_WS (6 * MAB)
#define MAIN_SMEM (6 * MAB + 1024)          // 56320

__global__ __launch_bounds__(128, 4) void main_mma_kernel(
    const float* __restrict__ wI, float* __restrict__ out) {
  extern __shared__ __align__(16) char smem[];
  float* ws = (float*)(smem + M_WS);

  const int tid = threadIdx.x, wid = tid >> 5, lane = tid & 31;
  const int g = lane >> 2, q4 = lane & 3;
  const int mwarp = (wid >> 1) * 32, nwarp = (wid & 1) * 32;
  const int b = blockIdx.z, q0 = blockIdx.y * 64, k0 = blockIdx.x * 64;

  const int aRow = (lane & 7) + (lane & 8);
  const int aCol = (lane & 16) ? 8 : 0;
  const int bRow = (lane & 7) + ((lane & 16) ? 8 : 0);
  const int bCol = (lane & 8) ? 8 : 0;

  auto issueA = [&](int h) {
    char* st = smem + (h & 1) * 2 * MAB;
    size_t base = ((size_t)h * ROWS + b * TQDIM + q0) * 64;
#pragma unroll
    for (int l = 0; l < 4; l++) {
      int idx = tid + l * 128, m = idx >> 3, c = idx & 7;
      cp16(st + m * 144 + c * 16, g_qIh + base + (size_t)m * 64 + c * 8);
      cp16(st + MAB + m * 144 + c * 16, g_qIl + base + (size_t)m * 64 + c * 8);
    }
  };

  // prologue: group0 = B + A(0); group1 = A(1)
  {
    char* st = smem + M_B;
    size_t base = ((size_t)b * TKDIM + k0) * 64;
#pragma unroll
    for (int l = 0; l < 4; l++) {
      int idx = tid + l * 128, m = idx >> 3, c = idx & 7;
      cp16(st + m * 144 + c * 16, g_kIh + base + (size_t)m * 64 + c * 8);
      cp16(st + MAB + m * 144 + c * 16, g_kIl + base + (size_t)m * 64 + c * 8);
    }
  }
  issueA(0);
  CP_COMMIT();
  issueA(1);
  CP_COMMIT();
  if (tid < 64)
    *(float4*)&ws[tid * 4] =
        *(const float4*)&wI[(size_t)(b * TQDIM + q0 + tid) * 4];

  const __nv_bfloat16* Bh = (const __nv_bfloat16*)(smem + M_B);
  const __nv_bfloat16* Bl = (const __nv_bfloat16*)(smem + M_B + MAB);

  float acc[2][4][4] = {};

  for (int h = 0; h < NHEADS; h++) {
    if (h + 1 < NHEADS) { CP_WAIT(1); } else { CP_WAIT(0); }
    __syncthreads();
    const __nv_bfloat16* Ah = (const __nv_bfloat16*)(smem + (h & 1) * 2 * MAB);
    const __nv_bfloat16* Al = (const __nv_bfloat16*)((const char*)Ah + MAB);

    float dot[2][4][4] = {};
#pragma unroll
    for (int ks = 0; ks < 4; ks++) {
      uint32_t ah[2][4], al[2][4];
#pragma unroll
      for (int mf = 0; mf < 2; mf++) {
        ldmx4(ah[mf], Ah + (mwarp + mf * 16 + aRow) * MSP + ks * 16 + aCol);
        ldmx4(al[mf], Al + (mwarp + mf * 16 + aRow) * MSP + ks * 16 + aCol);
      }
#pragma unroll
      for (int p = 0; p < 2; p++) {
        uint32_t bh[4], bl[4];
        ldmx4(bh, Bh + (nwarp + p * 16 + bRow) * MSP + ks * 16 + bCol);
        ldmx4(bl, Bl + (nwarp + p * 16 + bRow) * MSP + ks * 16 + bCol);
#pragma unroll
        for (int mf = 0; mf < 2; mf++) {
          mma_bf16(dot[mf][2 * p], ah[mf], bh[0], bh[1]);
          mma_bf16(dot[mf][2 * p], ah[mf], bl[0], bl[1]);
          mma_bf16(dot[mf][2 * p], al[mf], bh[0], bh[1]);
          mma_bf16(dot[mf][2 * p + 1], ah[mf], bh[2], bh[3]);
          mma_bf16(dot[mf][2 * p + 1], ah[mf], bl[2], bl[3]);
          mma_bf16(dot[mf][2 * p + 1], al[mf], bh[2], bh[3]);
        }
      }
    }
    // relu + weighted accumulate
#pragma unroll
    for (int mf = 0; mf < 2; mf++) {
      float wa = ws[(mwarp + mf * 16 + g) * 4 + h];
      float wb = ws[(mwarp + mf * 16 + g + 8) * 4 + h];
#pragma unroll
      for (int nf = 0; nf < 4; nf++) {
        acc[mf][nf][0] = fmaf(wa, fmaxf(dot[mf][nf][0], 0.f), acc[mf][nf][0]);
        acc[mf][nf][1] = fmaf(wa, fmaxf(dot[mf][nf][1], 0.f), acc[mf][nf][1]);
        acc[mf][nf][2] = fmaf(wb, fmaxf(dot[mf][nf][2], 0.f), acc[mf][nf][2]);
        acc[mf][nf][3] = fmaf(wb, fmaxf(dot[mf][nf][3], 0.f), acc[mf][nf][3]);
      }
    }
    if (h + 2 < NHEADS) {
      __syncthreads();  // all warps done with buf (h&1)
      issueA(h + 2);
      CP_COMMIT();
    }
  }

  float* obase = out + (size_t)(b * TQDIM + q0) * TKDIM + k0;
#pragma unroll
  for (int mf = 0; mf < 2; mf++) {
    int r0 = mwarp + mf * 16 + g;
#pragma unroll
    for (int nf = 0; nf < 4; nf++) {
      int col = nwarp + nf * 8 + q4 * 2;
      *(float2*)&obase[(size_t)r0 * TKDIM + col] =
          make_float2(acc[mf][nf][0], acc[mf][nf][1]);
      *(float2*)&obase[(size_t)(r0 + 8) * TKDIM + col] =
          make_float2(acc[mf][nf][2], acc[mf][nf][3]);
    }
  }
}

// ---------------------------------------------------------------------------
extern "C" void kernel_launch(void* const* d_in, const int* in_sizes, int n_in,
                              void* d_out, int out_size) {
  const float* x_q = (const float*)d_in[0];
  const float* x_k = (const float*)d_in[1];
  const float* Wq = (const float*)d_in[2];
  const float* Ww = (const float*)d_in[3];
  const float* Wk = (const float*)d_in[4];
  float* out = (float*)d_out;

  float* wI;
  cudaGetSymbolAddress((void**)&wI, g_wI);

  cudaFuncSetAttribute(proj_kernel, cudaFuncAttributeMaxDynamicSharedMemorySize,
                       PROJ_SMEM);
  cudaFuncSetAttribute(main_mma_kernel,
                       cudaFuncAttributeMaxDynamicSharedMemorySize, MAIN_SMEM);

  prep_kernel<<<19968, 256>>>(x_q, x_k, Wq, Ww, Wk);
  proj_kernel<<<640, 128, PROJ_SMEM>>>();
  main_mma_kernel<<<dim3(TKDIM / 64, TQDIM / 64, 2), 128, MAIN_SMEM>>>(wI,
                                                                       out);
}

// round 13
// speedup vs baseline: 1.1713x; 1.0337x over previous
#include <cuda_runtime.h>
#include <cuda_bf16.h>
#include <cstdint>

// Shapes (fixed)
#define TQDIM 4096
#define TKDIM 4096
#define DMODEL 2048
#define NHEADS 4
#define ROWS 8192  // B*T

// Weight transpose pre-split (tiny); [n][k], n<256: Wq col, n>=256: Wk col
__device__ __nv_bfloat16 g_Wth[320 * DMODEL];
__device__ __nv_bfloat16 g_Wtl[320 * DMODEL];
// Projection outputs (hi/lo bf16); q head-major [h][row][64]
__device__ __nv_bfloat16 g_qIh[NHEADS * ROWS * 64];
__device__ __nv_bfloat16 g_qIl[NHEADS * ROWS * 64];
__device__ __nv_bfloat16 g_kIh[ROWS * 64];
__device__ __nv_bfloat16 g_kIl[ROWS * 64];
__device__ float g_wI[ROWS * 4];

// ---------------------------------------------------------------------------
// helpers
// ---------------------------------------------------------------------------
__device__ __forceinline__ void split1(float v, __nv_bfloat16& h,
                                       __nv_bfloat16& l) {
  h = __float2bfloat16(v);
  l = __float2bfloat16(v - __bfloat162float(h));
}
__device__ __forceinline__ uint32_t pack2(__nv_bfloat16 a, __nv_bfloat16 b) {
  return (uint32_t)__bfloat16_as_ushort(a) |
         ((uint32_t)__bfloat16_as_ushort(b) << 16);
}
// packed float2 -> bf16x2 (first arg -> low half), rn rounding
__device__ __forceinline__ uint32_t cvt2(float lo, float hi) {
  uint32_t r;
  asm("cvt.rn.bf16x2.f32 %0, %1, %2;" : "=r"(r) : "f"(hi), "f"(lo));
  return r;
}
// build hi word + lo(residual) word from two fp32 (same rounding as split1)
__device__ __forceinline__ void split2w(float x, float y, uint32_t& h,
                                        uint32_t& l) {
  h = cvt2(x, y);
  float hx = __uint_as_float(h << 16);
  float hy = __uint_as_float(h & 0xffff0000u);
  l = cvt2(x - hx, y - hy);
}

__device__ __forceinline__ void mma_bf16(float* c, const uint32_t* a,
                                         uint32_t b0, uint32_t b1) {
  asm volatile(
      "mma.sync.aligned.m16n8k16.row.col.f32.bf16.bf16.f32 "
      "{%0,%1,%2,%3}, {%4,%5,%6,%7}, {%8,%9}, {%0,%1,%2,%3};\n"
      : "+f"(c[0]), "+f"(c[1]), "+f"(c[2]), "+f"(c[3])
      : "r"(a[0]), "r"(a[1]), "r"(a[2]), "r"(a[3]), "r"(b0), "r"(b1));
}

__device__ __forceinline__ void ldmx4(uint32_t* r, const void* p) {
  uint32_t a = (uint32_t)__cvta_generic_to_shared(p);
  asm volatile(
      "ldmatrix.sync.aligned.m8n8.x4.shared.b16 {%0,%1,%2,%3}, [%4];"
      : "=r"(r[0]), "=r"(r[1]), "=r"(r[2]), "=r"(r[3])
      : "r"(a));
}

__device__ __forceinline__ void cp16(void* dst, const void* src) {
  uint32_t d = (uint32_t)__cvta_generic_to_shared(dst);
  asm volatile("cp.async.cg.shared.global [%0], [%1], 16;" :: "r"(d), "l"(src));
}
#define CP_COMMIT() asm volatile("cp.async.commit_group;" ::: "memory")
#define CP_WAIT(n) asm volatile("cp.async.wait_group %0;" :: "n"(n) : "memory")

// ---------------------------------------------------------------------------
// prep: [0,1024) wI = x_q @ Ww (one warp per row) | [1024,3584) Wt split
// ---------------------------------------------------------------------------
__global__ __launch_bounds__(256) void prep_kernel(
    const float* __restrict__ x_q, const float* __restrict__ Wq,
    const float* __restrict__ Ww, const float* __restrict__ Wk) {
  const int bx = blockIdx.x;
  const int tid = threadIdx.x;
  if (bx < 1024) {
    int row = bx * 8 + (tid >> 5);
    int lane = tid & 31;
    const float4* xr = (const float4*)(x_q + (size_t)row * DMODEL);
    float a0 = 0.f, a1 = 0.f, a2 = 0.f, a3 = 0.f;
#pragma unroll
    for (int i = 0; i < 16; i++) {
      int d4 = lane + i * 32;
      float4 v = xr[d4];
      int d = d4 * 4;
      float4 w;
      w = *(const float4*)&Ww[(d + 0) * 4];
      a0 = fmaf(v.x, w.x, a0); a1 = fmaf(v.x, w.y, a1);
      a2 = fmaf(v.x, w.z, a2); a3 = fmaf(v.x, w.w, a3);
      w = *(const float4*)&Ww[(d + 1) * 4];
      a0 = fmaf(v.y, w.x, a0); a1 = fmaf(v.y, w.y, a1);
      a2 = fmaf(v.y, w.z, a2); a3 = fmaf(v.y, w.w, a3);
      w = *(const float4*)&Ww[(d + 2) * 4];
      a0 = fmaf(v.z, w.x, a0); a1 = fmaf(v.z, w.y, a1);
      a2 = fmaf(v.z, w.z, a2); a3 = fmaf(v.z, w.w, a3);
      w = *(const float4*)&Ww[(d + 3) * 4];
      a0 = fmaf(v.w, w.x, a0); a1 = fmaf(v.w, w.y, a1);
      a2 = fmaf(v.w, w.z, a2); a3 = fmaf(v.w, w.w, a3);
    }
#pragma unroll
    for (int off = 16; off; off >>= 1) {
      a0 += __shfl_down_sync(0xffffffffu, a0, off);
      a1 += __shfl_down_sync(0xffffffffu, a1, off);
      a2 += __shfl_down_sync(0xffffffffu, a2, off);
      a3 += __shfl_down_sync(0xffffffffu, a3, off);
    }
    if (lane == 0)
      *(float4*)&g_wI[(size_t)row * 4] = make_float4(a0, a1, a2, a3);
  } else {
    // Wt[n][k] = W[k][n], hi/lo split
    int idx = bx - 1024;        // 0..2559
    int n = idx >> 3;           // 0..319
    int k = (idx & 7) * 256 + tid;
    float v =
        (n < 256) ? Wq[(size_t)k * 256 + n] : Wk[(size_t)k * 64 + (n - 256)];
    __nv_bfloat16 h, l;
    split1(v, h, l);
    g_Wth[(size_t)n * DMODEL + k] = h;
    g_Wtl[(size_t)n * DMODEL + k] = l;
  }
}

// ---------------------------------------------------------------------------
// Projection: C = A(fp32 x) @ Wt^T, bf16x3 HMMA with in-register A split.
// CTA 64 x 64, 4 warps (2x2 of 32x32), K-chunk 32, 3-stage cp.async ring.
// Stage: A fp32 64x32 (rows padded to 36 floats) + B hi/lo bf16 (PSP=40).
// Grid 640: blocks 0..511: q (m0=(bx>>2)*64, nb=(bx&3)*64); 512..639: k.
// ---------------------------------------------------------------------------
#define PSP 40                    // B tile stride in halves (80 B rows)
#define PAROW 36                  // A fp32 row stride in floats (144 B)
#define PA_BYTES (64 * PAROW * 4) // 9216
#define PB_BYTES (64 * 80)        // 5120 per B subtile
#define PSTG (PA_BYTES + 2 * PB_BYTES)  // 19456
#define PROJ_SMEM (3 * PSTG)            // 58368

__global__ __launch_bounds__(128, 3) void proj_kernel(
    const float* __restrict__ xq, const float* __restrict__ xk) {
  extern __shared__ __align__(16) char smem[];
  const int bx = blockIdx.x;
  const bool isQ = bx < 512;
  const int m0 = isQ ? (bx >> 2) * 64 : (bx - 512) * 64;
  const int nb = isQ ? (bx & 3) * 64 : 256;  // Wt row base
  const float* A = isQ ? xq : xk;

  const int tid = threadIdx.x, wid = tid >> 5, lane = tid & 31;
  const int g = lane >> 2, q4 = lane & 3;
  const int mwarp = (wid >> 1) * 32, nwarp = (wid & 1) * 32;

  const int bRow = (lane & 7) + ((lane & 16) ? 8 : 0);
  const int bCol = (lane & 8) ? 8 : 0;

  auto issue = [&](int kc) {
    char* st = smem + (kc % 3) * PSTG;
    // A: 64 rows x 32 floats (8 x 16B chunks per row), 512 chunks
#pragma unroll
    for (int l = 0; l < 4; l++) {
      int idx = tid + l * 128, m = idx >> 3, c = idx & 7;
      cp16(st + m * 144 + c * 16,
           A + (size_t)(m0 + m) * DMODEL + kc * 32 + c * 4);
    }
    // B: 64 rows x 32 halves hi/lo (4 x 16B chunks per row), 256 chunks each
#pragma unroll
    for (int l = 0; l < 2; l++) {
      int idx = tid + l * 128, n = idx >> 2, c = idx & 3;
      size_t src = (size_t)(nb + n) * DMODEL + kc * 32 + c * 8;
      cp16(st + PA_BYTES + n * 80 + c * 16, g_Wth + src);
      cp16(st + PA_BYTES + PB_BYTES + n * 80 + c * 16, g_Wtl + src);
    }
    CP_COMMIT();
  };

  issue(0);
  issue(1);

  float dot[2][4][4] = {};
  const int NKC = DMODEL / 32;  // 64

  for (int kc = 0; kc < NKC; kc++) {
    if (kc + 1 < NKC) { CP_WAIT(1); } else { CP_WAIT(0); }
    __syncthreads();  // all warps done with buf (kc+2)%3
    if (kc + 2 < NKC) issue(kc + 2);

    const char* st = smem + (kc % 3) * PSTG;
    const float* Fa = (const float*)st;
    const __nv_bfloat16* Bh = (const __nv_bfloat16*)(st + PA_BYTES);
    const __nv_bfloat16* Bl = (const __nv_bfloat16*)(st + PA_BYTES + PB_BYTES);

#pragma unroll
    for (int ks = 0; ks < 2; ks++) {
      uint32_t ah[2][4], al[2][4];
#pragma unroll
      for (int mf = 0; mf < 2; mf++) {
        const float* p0 = Fa + (mwarp + mf * 16 + g) * PAROW + ks * 16 + 2 * q4;
        float2 v00 = *(const float2*)(p0);            // row r0, k lo
        float2 v10 = *(const float2*)(p0 + 8 * PAROW);// row r0+8, k lo
        float2 v01 = *(const float2*)(p0 + 8);        // row r0, k hi
        float2 v11 = *(const float2*)(p0 + 8 * PAROW + 8);
        split2w(v00.x, v00.y, ah[mf][0], al[mf][0]);
        split2w(v10.x, v10.y, ah[mf][1], al[mf][1]);
        split2w(v01.x, v01.y, ah[mf][2], al[mf][2]);
        split2w(v11.x, v11.y, ah[mf][3], al[mf][3]);
      }
#pragma unroll
      for (int p = 0; p < 2; p++) {
        uint32_t bh[4], bl[4];
        ldmx4(bh, Bh + (nwarp + p * 16 + bRow) * PSP + ks * 16 + bCol);
        ldmx4(bl, Bl + (nwarp + p * 16 + bRow) * PSP + ks * 16 + bCol);
#pragma unroll
        for (int mf = 0; mf < 2; mf++) {
          mma_bf16(dot[mf][2 * p], ah[mf], bh[0], bh[1]);
          mma_bf16(dot[mf][2 * p], ah[mf], bl[0], bl[1]);
          mma_bf16(dot[mf][2 * p], al[mf], bh[0], bh[1]);
          mma_bf16(dot[mf][2 * p + 1], ah[mf], bh[2], bh[3]);
          mma_bf16(dot[mf][2 * p + 1], ah[mf], bl[2], bl[3]);
          mma_bf16(dot[mf][2 * p + 1], al[mf], bh[2], bh[3]);
        }
      }
    }
  }

  // epilogue: split to hi/lo bf16 and write
#pragma unroll
  for (int mf = 0; mf < 2; mf++) {
#pragma unroll
    for (int nf = 0; nf < 4; nf++) {
      int grow = m0 + mwarp + mf * 16 + g;
      __nv_bfloat16 h0, l0, h1, l1;
      if (isQ) {
        int ncol = nb + nwarp + nf * 8 + q4 * 2;  // global Wq col (0..255)
        int head = ncol >> 6, hcol = ncol & 63;
        __nv_bfloat16* Oh = g_qIh + ((size_t)head * ROWS + grow) * 64 + hcol;
        __nv_bfloat16* Ol = g_qIl + ((size_t)head * ROWS + grow) * 64 + hcol;
        split1(dot[mf][nf][0], h0, l0);
        split1(dot[mf][nf][1], h1, l1);
        *(uint32_t*)Oh = pack2(h0, h1);
        *(uint32_t*)Ol = pack2(l0, l1);
        split1(dot[mf][nf][2], h0, l0);
        split1(dot[mf][nf][3], h1, l1);
        *(uint32_t*)(Oh + 8 * 64) = pack2(h0, h1);
        *(uint32_t*)(Ol + 8 * 64) = pack2(l0, l1);
      } else {
        int ncol = nwarp + nf * 8 + q4 * 2;
        __nv_bfloat16* Oh = g_kIh + (size_t)grow * 64 + ncol;
        __nv_bfloat16* Ol = g_kIl + (size_t)grow * 64 + ncol;
        split1(dot[mf][nf][0], h0, l0);
        split1(dot[mf][nf][1], h1, l1);
        *(uint32_t*)Oh = pack2(h0, h1);
        *(uint32_t*)Ol = pack2(l0, l1);
        split1(dot[mf][nf][2], h0, l0);
        split1(dot[mf][nf][3], h1, l1);
        *(uint32_t*)(Oh + 8 * 64) = pack2(h0, h1);
        *(uint32_t*)(Ol + 8 * 64) = pack2(l0, l1);
      }
    }
  }
}

// ---------------------------------------------------------------------------
// Main: CTA 64q x 64k, 128 threads (4 warps, 2x2 of 32x32), 4 CTAs/SM.
// A (q head) hi/lo double-buffered cp.async; B (k) fixed; per head:
// dot (bf16x3) -> relu -> w-weighted accumulate.
// ---------------------------------------------------------------------------
#define MSP 72
#define MAB (64 * MSP * 2)                  // 9216
#define M_B (4 * MAB)                       // B hi at 4*MAB, lo at 5*MAB
#define M_WS (6 * MAB)
#define MAIN_SMEM (6 * MAB + 1024)          // 56320

__global__ __launch_bounds__(128, 4) void main_mma_kernel(
    const float* __restrict__ wI, float* __restrict__ out) {
  extern __shared__ __align__(16) char smem[];
  float* ws = (float*)(smem + M_WS);

  const int tid = threadIdx.x, wid = tid >> 5, lane = tid & 31;
  const int g = lane >> 2, q4 = lane & 3;
  const int mwarp = (wid >> 1) * 32, nwarp = (wid & 1) * 32;
  const int b = blockIdx.z, q0 = blockIdx.y * 64, k0 = blockIdx.x * 64;

  const int aRow = (lane & 7) + (lane & 8);
  const int aCol = (lane & 16) ? 8 : 0;
  const int bRow = (lane & 7) + ((lane & 16) ? 8 : 0);
  const int bCol = (lane & 8) ? 8 : 0;

  auto issueA = [&](int h) {
    char* st = smem + (h & 1) * 2 * MAB;
    size_t base = ((size_t)h * ROWS + b * TQDIM + q0) * 64;
#pragma unroll
    for (int l = 0; l < 4; l++) {
      int idx = tid + l * 128, m = idx >> 3, c = idx & 7;
      cp16(st + m * 144 + c * 16, g_qIh + base + (size_t)m * 64 + c * 8);
      cp16(st + MAB + m * 144 + c * 16, g_qIl + base + (size_t)m * 64 + c * 8);
    }
  };

  // prologue: group0 = B + A(0); group1 = A(1)
  {
    char* st = smem + M_B;
    size_t base = ((size_t)b * TKDIM + k0) * 64;
#pragma unroll
    for (int l = 0; l < 4; l++) {
      int idx = tid + l * 128, m = idx >> 3, c = idx & 7;
      cp16(st + m * 144 + c * 16, g_kIh + base + (size_t)m * 64 + c * 8);
      cp16(st + MAB + m * 144 + c * 16, g_kIl + base + (size_t)m * 64 + c * 8);
    }
  }
  issueA(0);
  CP_COMMIT();
  issueA(1);
  CP_COMMIT();
  if (tid < 64)
    *(float4*)&ws[tid * 4] =
        *(const float4*)&wI[(size_t)(b * TQDIM + q0 + tid) * 4];

  const __nv_bfloat16* Bh = (const __nv_bfloat16*)(smem + M_B);
  const __nv_bfloat16* Bl = (const __nv_bfloat16*)(smem + M_B + MAB);

  float acc[2][4][4] = {};

  for (int h = 0; h < NHEADS; h++) {
    if (h + 1 < NHEADS) { CP_WAIT(1); } else { CP_WAIT(0); }
    __syncthreads();
    const __nv_bfloat16* Ah = (const __nv_bfloat16*)(smem + (h & 1) * 2 * MAB);
    const __nv_bfloat16* Al = (const __nv_bfloat16*)((const char*)Ah + MAB);

    float dot[2][4][4] = {};
#pragma unroll
    for (int ks = 0; ks < 4; ks++) {
      uint32_t ah[2][4], al[2][4];
#pragma unroll
      for (int mf = 0; mf < 2; mf++) {
        ldmx4(ah[mf], Ah + (mwarp + mf * 16 + aRow) * MSP + ks * 16 + aCol);
        ldmx4(al[mf], Al + (mwarp + mf * 16 + aRow) * MSP + ks * 16 + aCol);
      }
#pragma unroll
      for (int p = 0; p < 2; p++) {
        uint32_t bh[4], bl[4];
        ldmx4(bh, Bh + (nwarp + p * 16 + bRow) * MSP + ks * 16 + bCol);
        ldmx4(bl, Bl + (nwarp + p * 16 + bRow) * MSP + ks * 16 + bCol);
#pragma unroll
        for (int mf = 0; mf < 2; mf++) {
          mma_bf16(dot[mf][2 * p], ah[mf], bh[0], bh[1]);
          mma_bf16(dot[mf][2 * p], ah[mf], bl[0], bl[1]);
          mma_bf16(dot[mf][2 * p], al[mf], bh[0], bh[1]);
          mma_bf16(dot[mf][2 * p + 1], ah[mf], bh[2], bh[3]);
          mma_bf16(dot[mf][2 * p + 1], ah[mf], bl[2], bl[3]);
          mma_bf16(dot[mf][2 * p + 1], al[mf], bh[2], bh[3]);
        }
      }
    }
    // relu + weighted accumulate
#pragma unroll
    for (int mf = 0; mf < 2; mf++) {
      float wa = ws[(mwarp + mf * 16 + g) * 4 + h];
      float wb = ws[(mwarp + mf * 16 + g + 8) * 4 + h];
#pragma unroll
      for (int nf = 0; nf < 4; nf++) {
        acc[mf][nf][0] = fmaf(wa, fmaxf(dot[mf][nf][0], 0.f), acc[mf][nf][0]);
        acc[mf][nf][1] = fmaf(wa, fmaxf(dot[mf][nf][1], 0.f), acc[mf][nf][1]);
        acc[mf][nf][2] = fmaf(wb, fmaxf(dot[mf][nf][2], 0.f), acc[mf][nf][2]);
        acc[mf][nf][3] = fmaf(wb, fmaxf(dot[mf][nf][3], 0.f), acc[mf][nf][3]);
      }
    }
    if (h + 2 < NHEADS) {
      __syncthreads();  // all warps done with buf (h&1)
      issueA(h + 2);
      CP_COMMIT();
    }
  }

  float* obase = out + (size_t)(b * TQDIM + q0) * TKDIM + k0;
#pragma unroll
  for (int mf = 0; mf < 2; mf++) {
    int r0 = mwarp + mf * 16 + g;
#pragma unroll
    for (int nf = 0; nf < 4; nf++) {
      int col = nwarp + nf * 8 + q4 * 2;
      *(float2*)&obase[(size_t)r0 * TKDIM + col] =
          make_float2(acc[mf][nf][0], acc[mf][nf][1]);
      *(float2*)&obase[(size_t)(r0 + 8) * TKDIM + col] =
          make_float2(acc[mf][nf][2], acc[mf][nf][3]);
    }
  }
}

// ---------------------------------------------------------------------------
extern "C" void kernel_launch(void* const* d_in, const int* in_sizes, int n_in,
                              void* d_out, int out_size) {
  const float* x_q = (const float*)d_in[0];
  const float* x_k = (const float*)d_in[1];
  const float* Wq = (const float*)d_in[2];
  const float* Ww = (const float*)d_in[3];
  const float* Wk = (const float*)d_in[4];
  float* out = (float*)d_out;

  float* wI;
  cudaGetSymbolAddress((void**)&wI, g_wI);

  cudaFuncSetAttribute(proj_kernel, cudaFuncAttributeMaxDynamicSharedMemorySize,
                       PROJ_SMEM);
  cudaFuncSetAttribute(main_mma_kernel,
                       cudaFuncAttributeMaxDynamicSharedMemorySize, MAIN_SMEM);

  prep_kernel<<<3584, 256>>>(x_q, Wq, Ww, Wk);
  proj_kernel<<<640, 128, PROJ_SMEM>>>(x_q, x_k);
  main_mma_kernel<<<dim3(TKDIM / 64, TQDIM / 64, 2), 128, MAIN_SMEM>>>(wI,
                                                                       out);
}

// round 14
// speedup vs baseline: 1.1872x; 1.0136x over previous
#include <cuda_runtime.h>
#include <cuda_bf16.h>
#include <cstdint>

// Shapes (fixed)
#define TQDIM 4096
#define TKDIM 4096
#define DMODEL 2048
#define NHEADS 4
#define ROWS 8192  // B*T

// Weight transpose pre-split (tiny); [n][k], n<256: Wq col, n>=256: Wk col
__device__ __nv_bfloat16 g_Wth[320 * DMODEL];
__device__ __nv_bfloat16 g_Wtl[320 * DMODEL];
// Projection outputs (hi/lo bf16); q head-major [h][row][64]
__device__ __nv_bfloat16 g_qIh[NHEADS * ROWS * 64];
__device__ __nv_bfloat16 g_qIl[NHEADS * ROWS * 64];
__device__ __nv_bfloat16 g_kIh[ROWS * 64];
__device__ __nv_bfloat16 g_kIl[ROWS * 64];
__device__ float g_wI[ROWS * 4];

// ---------------------------------------------------------------------------
// helpers
// ---------------------------------------------------------------------------
__device__ __forceinline__ void split1(float v, __nv_bfloat16& h,
                                       __nv_bfloat16& l) {
  h = __float2bfloat16(v);
  l = __float2bfloat16(v - __bfloat162float(h));
}
__device__ __forceinline__ uint32_t pack2(__nv_bfloat16 a, __nv_bfloat16 b) {
  return (uint32_t)__bfloat16_as_ushort(a) |
         ((uint32_t)__bfloat16_as_ushort(b) << 16);
}
// packed float2 -> bf16x2 (first arg -> low half), rn rounding
__device__ __forceinline__ uint32_t cvt2(float lo, float hi) {
  uint32_t r;
  asm("cvt.rn.bf16x2.f32 %0, %1, %2;" : "=r"(r) : "f"(hi), "f"(lo));
  return r;
}
// build hi word + lo(residual) word from two fp32 (same rounding as split1)
__device__ __forceinline__ void split2w(float x, float y, uint32_t& h,
                                        uint32_t& l) {
  h = cvt2(x, y);
  float hx = __uint_as_float(h << 16);
  float hy = __uint_as_float(h & 0xffff0000u);
  l = cvt2(x - hx, y - hy);
}

__device__ __forceinline__ void mma_bf16(float* c, const uint32_t* a,
                                         uint32_t b0, uint32_t b1) {
  asm volatile(
      "mma.sync.aligned.m16n8k16.row.col.f32.bf16.bf16.f32 "
      "{%0,%1,%2,%3}, {%4,%5,%6,%7}, {%8,%9}, {%0,%1,%2,%3};\n"
      : "+f"(c[0]), "+f"(c[1]), "+f"(c[2]), "+f"(c[3])
      : "r"(a[0]), "r"(a[1]), "r"(a[2]), "r"(a[3]), "r"(b0), "r"(b1));
}

__device__ __forceinline__ void ldmx4(uint32_t* r, const void* p) {
  uint32_t a = (uint32_t)__cvta_generic_to_shared(p);
  asm volatile(
      "ldmatrix.sync.aligned.m8n8.x4.shared.b16 {%0,%1,%2,%3}, [%4];"
      : "=r"(r[0]), "=r"(r[1]), "=r"(r[2]), "=r"(r[3])
      : "r"(a));
}

__device__ __forceinline__ void cp16(void* dst, const void* src) {
  uint32_t d = (uint32_t)__cvta_generic_to_shared(dst);
  asm volatile("cp.async.cg.shared.global [%0], [%1], 16;" :: "r"(d), "l"(src));
}
#define CP_COMMIT() asm volatile("cp.async.commit_group;" ::: "memory")
#define CP_WAIT(n) asm volatile("cp.async.wait_group %0;" :: "n"(n) : "memory")

// ---------------------------------------------------------------------------
// prep: Wt[n][k] = W[k][n] hi/lo split only (grid 2560)
// ---------------------------------------------------------------------------
__global__ __launch_bounds__(256) void prep_kernel(
    const float* __restrict__ Wq, const float* __restrict__ Wk) {
  int idx = blockIdx.x;        // 0..2559
  int n = idx >> 3;            // 0..319
  int k = (idx & 7) * 256 + threadIdx.x;
  float v =
      (n < 256) ? Wq[(size_t)k * 256 + n] : Wk[(size_t)k * 64 + (n - 256)];
  __nv_bfloat16 h, l;
  split1(v, h, l);
  g_Wth[(size_t)n * DMODEL + k] = h;
  g_Wtl[(size_t)n * DMODEL + k] = l;
}

// ---------------------------------------------------------------------------
// Projection: C = A(fp32 x) @ Wt^T, bf16x3 HMMA with in-register A split.
// CTA 64 x 64, 4 warps (2x2 of 32x32), K-chunk 32, 3-stage cp.async ring.
// q-CTAs with nb==0 additionally accumulate wI = x_q @ Ww from the staged
// fp32 A tile (fma pipe is idle in this MMA-bound kernel).
// Grid 640: blocks 0..511: q (m0=(bx>>2)*64, nb=(bx&3)*64); 512..639: k.
// ---------------------------------------------------------------------------
#define PSP 40                    // B tile stride in halves (80 B rows)
#define PAROW 36                  // A fp32 row stride in floats (144 B)
#define PA_BYTES (64 * PAROW * 4) // 9216
#define PB_BYTES (64 * 80)        // 5120 per B subtile
#define PSTG (PA_BYTES + 2 * PB_BYTES)  // 19456
#define PROJ_SMEM (3 * PSTG)            // 58368

__global__ __launch_bounds__(128, 3) void proj_kernel(
    const float* __restrict__ xq, const float* __restrict__ xk,
    const float* __restrict__ Ww) {
  extern __shared__ __align__(16) char smem[];
  const int bx = blockIdx.x;
  const bool isQ = bx < 512;
  const int m0 = isQ ? (bx >> 2) * 64 : (bx - 512) * 64;
  const int nb = isQ ? (bx & 3) * 64 : 256;  // Wt row base
  const float* A = isQ ? xq : xk;
  const bool doW = isQ && (bx & 3) == 0;

  const int tid = threadIdx.x, wid = tid >> 5, lane = tid & 31;
  const int g = lane >> 2, q4 = lane & 3;
  const int mwarp = (wid >> 1) * 32, nwarp = (wid & 1) * 32;

  const int bRow = (lane & 7) + ((lane & 16) ? 8 : 0);
  const int bCol = (lane & 8) ? 8 : 0;

  auto issue = [&](int kc) {
    char* st = smem + (kc % 3) * PSTG;
#pragma unroll
    for (int l = 0; l < 4; l++) {
      int idx = tid + l * 128, m = idx >> 3, c = idx & 7;
      cp16(st + m * 144 + c * 16,
           A + (size_t)(m0 + m) * DMODEL + kc * 32 + c * 4);
    }
#pragma unroll
    for (int l = 0; l < 2; l++) {
      int idx = tid + l * 128, n = idx >> 2, c = idx & 3;
      size_t src = (size_t)(nb + n) * DMODEL + kc * 32 + c * 8;
      cp16(st + PA_BYTES + n * 80 + c * 16, g_Wth + src);
      cp16(st + PA_BYTES + PB_BYTES + n * 80 + c * 16, g_Wtl + src);
    }
    CP_COMMIT();
  };

  issue(0);
  issue(1);

  float dot[2][4][4] = {};
  float wacc0 = 0.f, wacc1 = 0.f, wacc2 = 0.f, wacc3 = 0.f;
  const int wrow = tid >> 1;          // 0..63
  const int wkh = (tid & 1) * 16;     // k-half within chunk
  const int NKC = DMODEL / 32;  // 64

  for (int kc = 0; kc < NKC; kc++) {
    if (kc + 1 < NKC) { CP_WAIT(1); } else { CP_WAIT(0); }
    __syncthreads();  // all warps done with buf (kc+2)%3
    if (kc + 2 < NKC) issue(kc + 2);

    const char* st = smem + (kc % 3) * PSTG;
    const float* Fa = (const float*)st;
    const __nv_bfloat16* Bh = (const __nv_bfloat16*)(st + PA_BYTES);
    const __nv_bfloat16* Bl = (const __nv_bfloat16*)(st + PA_BYTES + PB_BYTES);

    if (doW) {
      const float* arow = Fa + wrow * PAROW + wkh;
      const float4* wwp = (const float4*)(Ww + (kc * 32 + wkh) * 4);
#pragma unroll
      for (int kk = 0; kk < 16; kk++) {
        float xv = arow[kk];
        float4 w = wwp[kk];
        wacc0 = fmaf(xv, w.x, wacc0);
        wacc1 = fmaf(xv, w.y, wacc1);
        wacc2 = fmaf(xv, w.z, wacc2);
        wacc3 = fmaf(xv, w.w, wacc3);
      }
    }

#pragma unroll
    for (int ks = 0; ks < 2; ks++) {
      uint32_t ah[2][4], al[2][4];
#pragma unroll
      for (int mf = 0; mf < 2; mf++) {
        const float* p0 = Fa + (mwarp + mf * 16 + g) * PAROW + ks * 16 + 2 * q4;
        float2 v00 = *(const float2*)(p0);
        float2 v10 = *(const float2*)(p0 + 8 * PAROW);
        float2 v01 = *(const float2*)(p0 + 8);
        float2 v11 = *(const float2*)(p0 + 8 * PAROW + 8);
        split2w(v00.x, v00.y, ah[mf][0], al[mf][0]);
        split2w(v10.x, v10.y, ah[mf][1], al[mf][1]);
        split2w(v01.x, v01.y, ah[mf][2], al[mf][2]);
        split2w(v11.x, v11.y, ah[mf][3], al[mf][3]);
      }
#pragma unroll
      for (int p = 0; p < 2; p++) {
        uint32_t bh[4], bl[4];
        ldmx4(bh, Bh + (nwarp + p * 16 + bRow) * PSP + ks * 16 + bCol);
        ldmx4(bl, Bl + (nwarp + p * 16 + bRow) * PSP + ks * 16 + bCol);
#pragma unroll
        for (int mf = 0; mf < 2; mf++) {
          mma_bf16(dot[mf][2 * p], ah[mf], bh[0], bh[1]);
          mma_bf16(dot[mf][2 * p], ah[mf], bl[0], bl[1]);
          mma_bf16(dot[mf][2 * p], al[mf], bh[0], bh[1]);
          mma_bf16(dot[mf][2 * p + 1], ah[mf], bh[2], bh[3]);
          mma_bf16(dot[mf][2 * p + 1], ah[mf], bl[2], bl[3]);
          mma_bf16(dot[mf][2 * p + 1], al[mf], bh[2], bh[3]);
        }
      }
    }
  }

  if (doW) {
    wacc0 += __shfl_xor_sync(0xffffffffu, wacc0, 1);
    wacc1 += __shfl_xor_sync(0xffffffffu, wacc1, 1);
    wacc2 += __shfl_xor_sync(0xffffffffu, wacc2, 1);
    wacc3 += __shfl_xor_sync(0xffffffffu, wacc3, 1);
    if ((tid & 1) == 0)
      *(float4*)&g_wI[(size_t)(m0 + wrow) * 4] =
          make_float4(wacc0, wacc1, wacc2, wacc3);
  }

  // epilogue: split to hi/lo bf16 and write
#pragma unroll
  for (int mf = 0; mf < 2; mf++) {
#pragma unroll
    for (int nf = 0; nf < 4; nf++) {
      int grow = m0 + mwarp + mf * 16 + g;
      __nv_bfloat16 h0, l0, h1, l1;
      if (isQ) {
        int ncol = nb + nwarp + nf * 8 + q4 * 2;  // global Wq col (0..255)
        int head = ncol >> 6, hcol = ncol & 63;
        __nv_bfloat16* Oh = g_qIh + ((size_t)head * ROWS + grow) * 64 + hcol;
        __nv_bfloat16* Ol = g_qIl + ((size_t)head * ROWS + grow) * 64 + hcol;
        split1(dot[mf][nf][0], h0, l0);
        split1(dot[mf][nf][1], h1, l1);
        *(uint32_t*)Oh = pack2(h0, h1);
        *(uint32_t*)Ol = pack2(l0, l1);
        split1(dot[mf][nf][2], h0, l0);
        split1(dot[mf][nf][3], h1, l1);
        *(uint32_t*)(Oh + 8 * 64) = pack2(h0, h1);
        *(uint32_t*)(Ol + 8 * 64) = pack2(l0, l1);
      } else {
        int ncol = nwarp + nf * 8 + q4 * 2;
        __nv_bfloat16* Oh = g_kIh + (size_t)grow * 64 + ncol;
        __nv_bfloat16* Ol = g_kIl + (size_t)grow * 64 + ncol;
        split1(dot[mf][nf][0], h0, l0);
        split1(dot[mf][nf][1], h1, l1);
        *(uint32_t*)Oh = pack2(h0, h1);
        *(uint32_t*)Ol = pack2(l0, l1);
        split1(dot[mf][nf][2], h0, l0);
        split1(dot[mf][nf][3], h1, l1);
        *(uint32_t*)(Oh + 8 * 64) = pack2(h0, h1);
        *(uint32_t*)(Ol + 8 * 64) = pack2(l0, l1);
      }
    }
  }
}

// ---------------------------------------------------------------------------
// Main: CTA 64q x 64k, 128 threads (4 warps, 2x2 of 32x32), 4 CTAs/SM.
// A (q head) hi/lo double-buffered cp.async; B (k) fixed; per head:
// dot (bf16x3) -> relu -> w-weighted accumulate.
// ---------------------------------------------------------------------------
#define MSP 72
#define MAB (64 * MSP * 2)                  // 9216
#define M_B (4 * MAB)                       // B hi at 4*MAB, lo at 5*MAB
#define M_WS (6 * MAB)
#define MAIN_SMEM (6 * MAB + 1024)          // 56320

__global__ __launch_bounds__(128, 4) void main_mma_kernel(
    const float* __restrict__ wI, float* __restrict__ out) {
  extern __shared__ __align__(16) char smem[];
  float* ws = (float*)(smem + M_WS);

  const int tid = threadIdx.x, wid = tid >> 5, lane = tid & 31;
  const int g = lane >> 2, q4 = lane & 3;
  const int mwarp = (wid >> 1) * 32, nwarp = (wid & 1) * 32;
  const int b = blockIdx.z, q0 = blockIdx.y * 64, k0 = blockIdx.x * 64;

  const int aRow = (lane & 7) + (lane & 8);
  const int aCol = (lane & 16) ? 8 : 0;
  const int bRow = (lane & 7) + ((lane & 16) ? 8 : 0);
  const int bCol = (lane & 8) ? 8 : 0;

  auto issueA = [&](int h) {
    char* st = smem + (h & 1) * 2 * MAB;
    size_t base = ((size_t)h * ROWS + b * TQDIM + q0) * 64;
#pragma unroll
    for (int l = 0; l < 4; l++) {
      int idx = tid + l * 128, m = idx >> 3, c = idx & 7;
      cp16(st + m * 144 + c * 16, g_qIh + base + (size_t)m * 64 + c * 8);
      cp16(st + MAB + m * 144 + c * 16, g_qIl + base + (size_t)m * 64 + c * 8);
    }
  };

  // prologue: group0 = B + A(0); group1 = A(1)
  {
    char* st = smem + M_B;
    size_t base = ((size_t)b * TKDIM + k0) * 64;
#pragma unroll
    for (int l = 0; l < 4; l++) {
      int idx = tid + l * 128, m = idx >> 3, c = idx & 7;
      cp16(st + m * 144 + c * 16, g_kIh + base + (size_t)m * 64 + c * 8);
      cp16(st + MAB + m * 144 + c * 16, g_kIl + base + (size_t)m * 64 + c * 8);
    }
  }
  issueA(0);
  CP_COMMIT();
  issueA(1);
  CP_COMMIT();
  if (tid < 64)
    *(float4*)&ws[tid * 4] =
        *(const float4*)&wI[(size_t)(b * TQDIM + q0 + tid) * 4];

  const __nv_bfloat16* Bh = (const __nv_bfloat16*)(smem + M_B);
  const __nv_bfloat16* Bl = (const __nv_bfloat16*)(smem + M_B + MAB);

  float acc[2][4][4] = {};

  for (int h = 0; h < NHEADS; h++) {
    if (h + 1 < NHEADS) { CP_WAIT(1); } else { CP_WAIT(0); }
    __syncthreads();
    const __nv_bfloat16* Ah = (const __nv_bfloat16*)(smem + (h & 1) * 2 * MAB);
    const __nv_bfloat16* Al = (const __nv_bfloat16*)((const char*)Ah + MAB);

    float dot[2][4][4] = {};
#pragma unroll
    for (int ks = 0; ks < 4; ks++) {
      uint32_t ah[2][4], al[2][4];
#pragma unroll
      for (int mf = 0; mf < 2; mf++) {
        ldmx4(ah[mf], Ah + (mwarp + mf * 16 + aRow) * MSP + ks * 16 + aCol);
        ldmx4(al[mf], Al + (mwarp + mf * 16 + aRow) * MSP + ks * 16 + aCol);
      }
#pragma unroll
      for (int p = 0; p < 2; p++) {
        uint32_t bh[4], bl[4];
        ldmx4(bh, Bh + (nwarp + p * 16 + bRow) * MSP + ks * 16 + bCol);
        ldmx4(bl, Bl + (nwarp + p * 16 + bRow) * MSP + ks * 16 + bCol);
#pragma unroll
        for (int mf = 0; mf < 2; mf++) {
          mma_bf16(dot[mf][2 * p], ah[mf], bh[0], bh[1]);
          mma_bf16(dot[mf][2 * p], ah[mf], bl[0], bl[1]);
          mma_bf16(dot[mf][2 * p], al[mf], bh[0], bh[1]);
          mma_bf16(dot[mf][2 * p + 1], ah[mf], bh[2], bh[3]);
          mma_bf16(dot[mf][2 * p + 1], ah[mf], bl[2], bl[3]);
          mma_bf16(dot[mf][2 * p + 1], al[mf], bh[2], bh[3]);
        }
      }
    }
    // relu + weighted accumulate
#pragma unroll
    for (int mf = 0; mf < 2; mf++) {
      float wa = ws[(mwarp + mf * 16 + g) * 4 + h];
      float wb = ws[(mwarp + mf * 16 + g + 8) * 4 + h];
#pragma unroll
      for (int nf = 0; nf < 4; nf++) {
        acc[mf][nf][0] = fmaf(wa, fmaxf(dot[mf][nf][0], 0.f), acc[mf][nf][0]);
        acc[mf][nf][1] = fmaf(wa, fmaxf(dot[mf][nf][1], 0.f), acc[mf][nf][1]);
        acc[mf][nf][2] = fmaf(wb, fmaxf(dot[mf][nf][2], 0.f), acc[mf][nf][2]);
        acc[mf][nf][3] = fmaf(wb, fmaxf(dot[mf][nf][3], 0.f), acc[mf][nf][3]);
      }
    }
    if (h + 2 < NHEADS) {
      __syncthreads();  // all warps done with buf (h&1)
      issueA(h + 2);
      CP_COMMIT();
    }
  }

  float* obase = out + (size_t)(b * TQDIM + q0) * TKDIM + k0;
#pragma unroll
  for (int mf = 0; mf < 2; mf++) {
    int r0 = mwarp + mf * 16 + g;
#pragma unroll
    for (int nf = 0; nf < 4; nf++) {
      int col = nwarp + nf * 8 + q4 * 2;
      *(float2*)&obase[(size_t)r0 * TKDIM + col] =
          make_float2(acc[mf][nf][0], acc[mf][nf][1]);
      *(float2*)&obase[(size_t)(r0 + 8) * TKDIM + col] =
          make_float2(acc[mf][nf][2], acc[mf][nf][3]);
    }
  }
}

// ---------------------------------------------------------------------------
extern "C" void kernel_launch(void* const* d_in, const int* in_sizes, int n_in,
                              void* d_out, int out_size) {
  const float* x_q = (const float*)d_in[0];
  const float* x_k = (const float*)d_in[1];
  const float* Wq = (const float*)d_in[2];
  const float* Ww = (const float*)d_in[3];
  const float* Wk = (const float*)d_in[4];
  float* out = (float*)d_out;

  float* wI;
  cudaGetSymbolAddress((void**)&wI, g_wI);

  cudaFuncSetAttribute(proj_kernel, cudaFuncAttributeMaxDynamicSharedMemorySize,
                       PROJ_SMEM);
  cudaFuncSetAttribute(main_mma_kernel,
                       cudaFuncAttributeMaxDynamicSharedMemorySize, MAIN_SMEM);

  prep_kernel<<<2560, 256>>>(Wq, Wk);
  proj_kernel<<<640, 128, PROJ_SMEM>>>(x_q, x_k, Ww);
  main_mma_kernel<<<dim3(TKDIM / 64, TQDIM / 64, 2), 128, MAIN_SMEM>>>(wI,
                                                                       out);
}

// round 15
// speedup vs baseline: 1.3426x; 1.1308x over previous
#include <cuda_runtime.h>
#include <cuda_fp16.h>
#include <cstdint>

// Shapes (fixed)
#define TQDIM 4096
#define TKDIM 4096
#define DMODEL 2048
#define NHEADS 4
#define ROWS 8192  // B*T

// Weight transpose, fp16; [n][k], n<256: Wq col, n>=256: Wk col
__device__ __half g_Wth[320 * DMODEL];
// Projection outputs; q: fp16 hi+lo (head-major [h][row][64]), k: fp16 hi only
__device__ __half g_qIh[NHEADS * ROWS * 64];
__device__ __half g_qIl[NHEADS * ROWS * 64];
__device__ __half g_kIh[ROWS * 64];
__device__ float g_wI[ROWS * 4];

// ---------------------------------------------------------------------------
// helpers
// ---------------------------------------------------------------------------
// pack two fp32 -> f16x2 (first arg -> low half), rn rounding
__device__ __forceinline__ uint32_t cvt2h(float lo, float hi) {
  uint32_t r;
  asm("cvt.rn.f16x2.f32 %0, %1, %2;" : "=r"(r) : "f"(hi), "f"(lo));
  return r;
}
// fp16 hi word + residual-lo word from two fp32
__device__ __forceinline__ void split2h(float x, float y, uint32_t& h,
                                        uint32_t& l) {
  h = cvt2h(x, y);
  __half2 hh = *reinterpret_cast<__half2*>(&h);
  float2 hf = __half22float2(hh);
  l = cvt2h(x - hf.x, y - hf.y);
}

__device__ __forceinline__ void mma_f16(float* c, const uint32_t* a,
                                        uint32_t b0, uint32_t b1) {
  asm volatile(
      "mma.sync.aligned.m16n8k16.row.col.f32.f16.f16.f32 "
      "{%0,%1,%2,%3}, {%4,%5,%6,%7}, {%8,%9}, {%0,%1,%2,%3};\n"
      : "+f"(c[0]), "+f"(c[1]), "+f"(c[2]), "+f"(c[3])
      : "r"(a[0]), "r"(a[1]), "r"(a[2]), "r"(a[3]), "r"(b0), "r"(b1));
}

__device__ __forceinline__ void ldmx4(uint32_t* r, const void* p) {
  uint32_t a = (uint32_t)__cvta_generic_to_shared(p);
  asm volatile(
      "ldmatrix.sync.aligned.m8n8.x4.shared.b16 {%0,%1,%2,%3}, [%4];"
      : "=r"(r[0]), "=r"(r[1]), "=r"(r[2]), "=r"(r[3])
      : "r"(a));
}

__device__ __forceinline__ void cp16(void* dst, const void* src) {
  uint32_t d = (uint32_t)__cvta_generic_to_shared(dst);
  asm volatile("cp.async.cg.shared.global [%0], [%1], 16;" :: "r"(d), "l"(src));
}
#define CP_COMMIT() asm volatile("cp.async.commit_group;" ::: "memory")
#define CP_WAIT(n) asm volatile("cp.async.wait_group %0;" :: "n"(n) : "memory")

// ---------------------------------------------------------------------------
// prep: Wt[n][k] = fp16(W[k][n]) (grid 2560)
// ---------------------------------------------------------------------------
__global__ __launch_bounds__(256) void prep_kernel(
    const float* __restrict__ Wq, const float* __restrict__ Wk) {
  int idx = blockIdx.x;        // 0..2559
  int n = idx >> 3;            // 0..319
  int k = (idx & 7) * 256 + threadIdx.x;
  float v =
      (n < 256) ? Wq[(size_t)k * 256 + n] : Wk[(size_t)k * 64 + (n - 256)];
  g_Wth[(size_t)n * DMODEL + k] = __float2half_rn(v);
}

// ---------------------------------------------------------------------------
// Projection: C = A(fp32 x) @ fp16(Wt)^T, fp16x2 HMMA (Ah*B + Al*B).
// CTA 64 x 64, 4 warps (2x2 of 32x32), K-chunk 32, 3-stage cp.async ring,
// 4 CTAs/SM (stage 14336 B). q-CTAs with nb==0 also accumulate wI.
// Grid 640: blocks 0..511: q (m0=(bx>>2)*64, nb=(bx&3)*64); 512..639: k.
// ---------------------------------------------------------------------------
#define PSP 40                    // B tile stride in halves (80 B rows)
#define PAROW 36                  // A fp32 row stride in floats (144 B)
#define PA_BYTES (64 * PAROW * 4) // 9216
#define PB_BYTES (64 * 80)        // 5120
#define PSTG (PA_BYTES + PB_BYTES)      // 14336
#define PROJ_SMEM (3 * PSTG)            // 43008

__global__ __launch_bounds__(128, 4) void proj_kernel(
    const float* __restrict__ xq, const float* __restrict__ xk,
    const float* __restrict__ Ww) {
  extern __shared__ __align__(16) char smem[];
  const int bx = blockIdx.x;
  const bool isQ = bx < 512;
  const int m0 = isQ ? (bx >> 2) * 64 : (bx - 512) * 64;
  const int nb = isQ ? (bx & 3) * 64 : 256;  // Wt row base
  const float* A = isQ ? xq : xk;
  const bool doW = isQ && (bx & 3) == 0;

  const int tid = threadIdx.x, wid = tid >> 5, lane = tid & 31;
  const int g = lane >> 2, q4 = lane & 3;
  const int mwarp = (wid >> 1) * 32, nwarp = (wid & 1) * 32;

  const int bRow = (lane & 7) + ((lane & 16) ? 8 : 0);
  const int bCol = (lane & 8) ? 8 : 0;

  auto issue = [&](int kc) {
    char* st = smem + (kc % 3) * PSTG;
#pragma unroll
    for (int l = 0; l < 4; l++) {
      int idx = tid + l * 128, m = idx >> 3, c = idx & 7;
      cp16(st + m * 144 + c * 16,
           A + (size_t)(m0 + m) * DMODEL + kc * 32 + c * 4);
    }
#pragma unroll
    for (int l = 0; l < 2; l++) {
      int idx = tid + l * 128, n = idx >> 2, c = idx & 3;
      cp16(st + PA_BYTES + n * 80 + c * 16,
           g_Wth + (size_t)(nb + n) * DMODEL + kc * 32 + c * 8);
    }
    CP_COMMIT();
  };

  issue(0);
  issue(1);

  float dot[2][4][4] = {};
  float wacc0 = 0.f, wacc1 = 0.f, wacc2 = 0.f, wacc3 = 0.f;
  const int wrow = tid >> 1;          // 0..63
  const int wkh = (tid & 1) * 16;     // k-half within chunk
  const int NKC = DMODEL / 32;  // 64

  for (int kc = 0; kc < NKC; kc++) {
    if (kc + 1 < NKC) { CP_WAIT(1); } else { CP_WAIT(0); }
    __syncthreads();  // all warps done with buf (kc+2)%3
    if (kc + 2 < NKC) issue(kc + 2);

    const char* st = smem + (kc % 3) * PSTG;
    const float* Fa = (const float*)st;
    const __half* Bh = (const __half*)(st + PA_BYTES);

    if (doW) {
      const float* arow = Fa + wrow * PAROW + wkh;
      const float4* wwp = (const float4*)(Ww + (kc * 32 + wkh) * 4);
#pragma unroll
      for (int kk = 0; kk < 16; kk++) {
        float xv = arow[kk];
        float4 w = wwp[kk];
        wacc0 = fmaf(xv, w.x, wacc0);
        wacc1 = fmaf(xv, w.y, wacc1);
        wacc2 = fmaf(xv, w.z, wacc2);
        wacc3 = fmaf(xv, w.w, wacc3);
      }
    }

#pragma unroll
    for (int ks = 0; ks < 2; ks++) {
      uint32_t ah[2][4], al[2][4];
#pragma unroll
      for (int mf = 0; mf < 2; mf++) {
        const float* p0 = Fa + (mwarp + mf * 16 + g) * PAROW + ks * 16 + 2 * q4;
        float2 v00 = *(const float2*)(p0);
        float2 v10 = *(const float2*)(p0 + 8 * PAROW);
        float2 v01 = *(const float2*)(p0 + 8);
        float2 v11 = *(const float2*)(p0 + 8 * PAROW + 8);
        split2h(v00.x, v00.y, ah[mf][0], al[mf][0]);
        split2h(v10.x, v10.y, ah[mf][1], al[mf][1]);
        split2h(v01.x, v01.y, ah[mf][2], al[mf][2]);
        split2h(v11.x, v11.y, ah[mf][3], al[mf][3]);
      }
#pragma unroll
      for (int p = 0; p < 2; p++) {
        uint32_t bh[4];
        ldmx4(bh, Bh + (nwarp + p * 16 + bRow) * PSP + ks * 16 + bCol);
#pragma unroll
        for (int mf = 0; mf < 2; mf++) {
          mma_f16(dot[mf][2 * p], ah[mf], bh[0], bh[1]);
          mma_f16(dot[mf][2 * p], al[mf], bh[0], bh[1]);
          mma_f16(dot[mf][2 * p + 1], ah[mf], bh[2], bh[3]);
          mma_f16(dot[mf][2 * p + 1], al[mf], bh[2], bh[3]);
        }
      }
    }
  }

  if (doW) {
    wacc0 += __shfl_xor_sync(0xffffffffu, wacc0, 1);
    wacc1 += __shfl_xor_sync(0xffffffffu, wacc1, 1);
    wacc2 += __shfl_xor_sync(0xffffffffu, wacc2, 1);
    wacc3 += __shfl_xor_sync(0xffffffffu, wacc3, 1);
    if ((tid & 1) == 0)
      *(float4*)&g_wI[(size_t)(m0 + wrow) * 4] =
          make_float4(wacc0, wacc1, wacc2, wacc3);
  }

  // epilogue: q -> fp16 hi+lo; k -> fp16 hi only
#pragma unroll
  for (int mf = 0; mf < 2; mf++) {
#pragma unroll
    for (int nf = 0; nf < 4; nf++) {
      int grow = m0 + mwarp + mf * 16 + g;
      if (isQ) {
        int ncol = nb + nwarp + nf * 8 + q4 * 2;  // global Wq col (0..255)
        int head = ncol >> 6, hcol = ncol & 63;
        __half* Oh = g_qIh + ((size_t)head * ROWS + grow) * 64 + hcol;
        __half* Ol = g_qIl + ((size_t)head * ROWS + grow) * 64 + hcol;
        uint32_t hw, lw;
        split2h(dot[mf][nf][0], dot[mf][nf][1], hw, lw);
        *(uint32_t*)Oh = hw;
        *(uint32_t*)Ol = lw;
        split2h(dot[mf][nf][2], dot[mf][nf][3], hw, lw);
        *(uint32_t*)(Oh + 8 * 64) = hw;
        *(uint32_t*)(Ol + 8 * 64) = lw;
      } else {
        int ncol = nwarp + nf * 8 + q4 * 2;
        __half* Oh = g_kIh + (size_t)grow * 64 + ncol;
        *(uint32_t*)Oh = cvt2h(dot[mf][nf][0], dot[mf][nf][1]);
        *(uint32_t*)(Oh + 8 * 64) = cvt2h(dot[mf][nf][2], dot[mf][nf][3]);
      }
    }
  }
}

// ---------------------------------------------------------------------------
// Main: CTA 64q x 64k, 128 threads (4 warps, 2x2 of 32x32), 4 CTAs/SM.
// A (q head) fp16 hi/lo double-buffered cp.async; B (k) fp16 hi only, fixed;
// per head: dot = qh*k + ql*k -> relu -> w-weighted accumulate.
// ---------------------------------------------------------------------------
#define MSP 72
#define MAB (64 * MSP * 2)                  // 9216
#define M_B (4 * MAB)                       // B at 4*MAB
#define M_WS (5 * MAB)
#define MAIN_SMEM (5 * MAB + 1024)          // 47104

__global__ __launch_bounds__(128, 4) void main_mma_kernel(
    const float* __restrict__ wI, float* __restrict__ out) {
  extern __shared__ __align__(16) char smem[];
  float* ws = (float*)(smem + M_WS);

  const int tid = threadIdx.x, wid = tid >> 5, lane = tid & 31;
  const int g = lane >> 2, q4 = lane & 3;
  const int mwarp = (wid >> 1) * 32, nwarp = (wid & 1) * 32;
  const int b = blockIdx.z, q0 = blockIdx.y * 64, k0 = blockIdx.x * 64;

  const int aRow = (lane & 7) + (lane & 8);
  const int aCol = (lane & 16) ? 8 : 0;
  const int bRow = (lane & 7) + ((lane & 16) ? 8 : 0);
  const int bCol = (lane & 8) ? 8 : 0;

  auto issueA = [&](int h) {
    char* st = smem + (h & 1) * 2 * MAB;
    size_t base = ((size_t)h * ROWS + b * TQDIM + q0) * 64;
#pragma unroll
    for (int l = 0; l < 4; l++) {
      int idx = tid + l * 128, m = idx >> 3, c = idx & 7;
      cp16(st + m * 144 + c * 16, g_qIh + base + (size_t)m * 64 + c * 8);
      cp16(st + MAB + m * 144 + c * 16, g_qIl + base + (size_t)m * 64 + c * 8);
    }
  };

  // prologue: group0 = B + A(0); group1 = A(1)
  {
    char* st = smem + M_B;
    size_t base = ((size_t)b * TKDIM + k0) * 64;
#pragma unroll
    for (int l = 0; l < 4; l++) {
      int idx = tid + l * 128, m = idx >> 3, c = idx & 7;
      cp16(st + m * 144 + c * 16, g_kIh + base + (size_t)m * 64 + c * 8);
    }
  }
  issueA(0);
  CP_COMMIT();
  issueA(1);
  CP_COMMIT();
  if (tid < 64)
    *(float4*)&ws[tid * 4] =
        *(const float4*)&wI[(size_t)(b * TQDIM + q0 + tid) * 4];

  const __half* Bh = (const __half*)(smem + M_B);

  float acc[2][4][4] = {};

  for (int h = 0; h < NHEADS; h++) {
    if (h + 1 < NHEADS) { CP_WAIT(1); } else { CP_WAIT(0); }
    __syncthreads();
    const __half* Ah = (const __half*)(smem + (h & 1) * 2 * MAB);
    const __half* Al = (const __half*)((const char*)Ah + MAB);

    float dot[2][4][4] = {};
#pragma unroll
    for (int ks = 0; ks < 4; ks++) {
      uint32_t ah[2][4], al[2][4];
#pragma unroll
      for (int mf = 0; mf < 2; mf++) {
        ldmx4(ah[mf], Ah + (mwarp + mf * 16 + aRow) * MSP + ks * 16 + aCol);
        ldmx4(al[mf], Al + (mwarp + mf * 16 + aRow) * MSP + ks * 16 + aCol);
      }
#pragma unroll
      for (int p = 0; p < 2; p++) {
        uint32_t bh[4];
        ldmx4(bh, Bh + (nwarp + p * 16 + bRow) * MSP + ks * 16 + bCol);
#pragma unroll
        for (int mf = 0; mf < 2; mf++) {
          mma_f16(dot[mf][2 * p], ah[mf], bh[0], bh[1]);
          mma_f16(dot[mf][2 * p], al[mf], bh[0], bh[1]);
          mma_f16(dot[mf][2 * p + 1], ah[mf], bh[2], bh[3]);
          mma_f16(dot[mf][2 * p + 1], al[mf], bh[2], bh[3]);
        }
      }
    }
    // relu + weighted accumulate
#pragma unroll
    for (int mf = 0; mf < 2; mf++) {
      float wa = ws[(mwarp + mf * 16 + g) * 4 + h];
      float wb = ws[(mwarp + mf * 16 + g + 8) * 4 + h];
#pragma unroll
      for (int nf = 0; nf < 4; nf++) {
        acc[mf][nf][0] = fmaf(wa, fmaxf(dot[mf][nf][0], 0.f), acc[mf][nf][0]);
        acc[mf][nf][1] = fmaf(wa, fmaxf(dot[mf][nf][1], 0.f), acc[mf][nf][1]);
        acc[mf][nf][2] = fmaf(wb, fmaxf(dot[mf][nf][2], 0.f), acc[mf][nf][2]);
        acc[mf][nf][3] = fmaf(wb, fmaxf(dot[mf][nf][3], 0.f), acc[mf][nf][3]);
      }
    }
    if (h + 2 < NHEADS) {
      __syncthreads();  // all warps done with buf (h&1)
      issueA(h + 2);
      CP_COMMIT();
    }
  }

  float* obase = out + (size_t)(b * TQDIM + q0) * TKDIM + k0;
#pragma unroll
  for (int mf = 0; mf < 2; mf++) {
    int r0 = mwarp + mf * 16 + g;
#pragma unroll
    for (int nf = 0; nf < 4; nf++) {
      int col = nwarp + nf * 8 + q4 * 2;
      *(float2*)&obase[(size_t)r0 * TKDIM + col] =
          make_float2(acc[mf][nf][0], acc[mf][nf][1]);
      *(float2*)&obase[(size_t)(r0 + 8) * TKDIM + col] =
          make_float2(acc[mf][nf][2], acc[mf][nf][3]);
    }
  }
}

// ---------------------------------------------------------------------------
extern "C" void kernel_launch(void* const* d_in, const int* in_sizes, int n_in,
                              void* d_out, int out_size) {
  const float* x_q = (const float*)d_in[0];
  const float* x_k = (const float*)d_in[1];
  const float* Wq = (const float*)d_in[2];
  const float* Ww = (const float*)d_in[3];
  const float* Wk = (const float*)d_in[4];
  float* out = (float*)d_out;

  float* wI;
  cudaGetSymbolAddress((void**)&wI, g_wI);

  cudaFuncSetAttribute(proj_kernel, cudaFuncAttributeMaxDynamicSharedMemorySize,
                       PROJ_SMEM);
  cudaFuncSetAttribute(main_mma_kernel,
                       cudaFuncAttributeMaxDynamicSharedMemorySize, MAIN_SMEM);

  prep_kernel<<<2560, 256>>>(Wq, Wk);
  proj_kernel<<<640, 128, PROJ_SMEM>>>(x_q, x_k, Ww);
  main_mma_kernel<<<dim3(TKDIM / 64, TQDIM / 64, 2), 128, MAIN_SMEM>>>(wI,
                                                                       out);
}

// round 16
// speedup vs baseline: 1.5349x; 1.1432x over previous
#include <cuda_runtime.h>
#include <cuda_fp16.h>
#include <cstdint>

// Shapes (fixed)
#define TQDIM 4096
#define TKDIM 4096
#define DMODEL 2048
#define NHEADS 4
#define ROWS 8192  // B*T

// Weight transpose, fp16; [n][k], n<256: Wq col, n>=256: Wk col
__device__ __half g_Wth[320 * DMODEL];
// Projection outputs, fp16; q head-major [h][row][64], k [row][64]
__device__ __half g_qIh[NHEADS * ROWS * 64];
__device__ __half g_kIh[ROWS * 64];
__device__ float g_wI[ROWS * 4];

// ---------------------------------------------------------------------------
// helpers
// ---------------------------------------------------------------------------
// pack two fp32 -> f16x2 (first arg -> low half), rn rounding
__device__ __forceinline__ uint32_t cvt2h(float lo, float hi) {
  uint32_t r;
  asm("cvt.rn.f16x2.f32 %0, %1, %2;" : "=r"(r) : "f"(hi), "f"(lo));
  return r;
}
// fp16 hi word + residual-lo word from two fp32
__device__ __forceinline__ void split2h(float x, float y, uint32_t& h,
                                        uint32_t& l) {
  h = cvt2h(x, y);
  __half2 hh = *reinterpret_cast<__half2*>(&h);
  float2 hf = __half22float2(hh);
  l = cvt2h(x - hf.x, y - hf.y);
}

__device__ __forceinline__ void mma_f16(float* c, const uint32_t* a,
                                        uint32_t b0, uint32_t b1) {
  asm volatile(
      "mma.sync.aligned.m16n8k16.row.col.f32.f16.f16.f32 "
      "{%0,%1,%2,%3}, {%4,%5,%6,%7}, {%8,%9}, {%0,%1,%2,%3};\n"
      : "+f"(c[0]), "+f"(c[1]), "+f"(c[2]), "+f"(c[3])
      : "r"(a[0]), "r"(a[1]), "r"(a[2]), "r"(a[3]), "r"(b0), "r"(b1));
}

__device__ __forceinline__ void ldmx4(uint32_t* r, const void* p) {
  uint32_t a = (uint32_t)__cvta_generic_to_shared(p);
  asm volatile(
      "ldmatrix.sync.aligned.m8n8.x4.shared.b16 {%0,%1,%2,%3}, [%4];"
      : "=r"(r[0]), "=r"(r[1]), "=r"(r[2]), "=r"(r[3])
      : "r"(a));
}

__device__ __forceinline__ void cp16(void* dst, const void* src) {
  uint32_t d = (uint32_t)__cvta_generic_to_shared(dst);
  asm volatile("cp.async.cg.shared.global [%0], [%1], 16;" :: "r"(d), "l"(src));
}
#define CP_COMMIT() asm volatile("cp.async.commit_group;" ::: "memory")
#define CP_WAIT(n) asm volatile("cp.async.wait_group %0;" :: "n"(n) : "memory")

// ---------------------------------------------------------------------------
// prep: Wt[n][k] = fp16(W[k][n]) (grid 2560)
// ---------------------------------------------------------------------------
__global__ __launch_bounds__(256) void prep_kernel(
    const float* __restrict__ Wq, const float* __restrict__ Wk) {
  int idx = blockIdx.x;        // 0..2559
  int n = idx >> 3;            // 0..319
  int k = (idx & 7) * 256 + threadIdx.x;
  float v =
      (n < 256) ? Wq[(size_t)k * 256 + n] : Wk[(size_t)k * 64 + (n - 256)];
  g_Wth[(size_t)n * DMODEL + k] = __float2half_rn(v);
}

// ---------------------------------------------------------------------------
// Projection: C = A(fp32 x) @ fp16(Wt)^T, fp16x2 HMMA (Ah*B + Al*B).
// CTA 64 x 64, 4 warps (2x2 of 32x32), K-chunk 32, 3-stage cp.async ring,
// 4 CTAs/SM (stage 14336 B). q-CTAs with nb==0 also accumulate wI.
// Outputs stored as single fp16.
// Grid 640: blocks 0..511: q (m0=(bx>>2)*64, nb=(bx&3)*64); 512..639: k.
// ---------------------------------------------------------------------------
#define PSP 40                    // B tile stride in halves (80 B rows)
#define PAROW 36                  // A fp32 row stride in floats (144 B)
#define PA_BYTES (64 * PAROW * 4) // 9216
#define PB_BYTES (64 * 80)        // 5120
#define PSTG (PA_BYTES + PB_BYTES)      // 14336
#define PROJ_SMEM (3 * PSTG)            // 43008

__global__ __launch_bounds__(128, 4) void proj_kernel(
    const float* __restrict__ xq, const float* __restrict__ xk,
    const float* __restrict__ Ww) {
  extern __shared__ __align__(16) char smem[];
  const int bx = blockIdx.x;
  const bool isQ = bx < 512;
  const int m0 = isQ ? (bx >> 2) * 64 : (bx - 512) * 64;
  const int nb = isQ ? (bx & 3) * 64 : 256;  // Wt row base
  const float* A = isQ ? xq : xk;
  const bool doW = isQ && (bx & 3) == 0;

  const int tid = threadIdx.x, wid = tid >> 5, lane = tid & 31;
  const int g = lane >> 2, q4 = lane & 3;
  const int mwarp = (wid >> 1) * 32, nwarp = (wid & 1) * 32;

  const int bRow = (lane & 7) + ((lane & 16) ? 8 : 0);
  const int bCol = (lane & 8) ? 8 : 0;

  auto issue = [&](int kc) {
    char* st = smem + (kc % 3) * PSTG;
#pragma unroll
    for (int l = 0; l < 4; l++) {
      int idx = tid + l * 128, m = idx >> 3, c = idx & 7;
      cp16(st + m * 144 + c * 16,
           A + (size_t)(m0 + m) * DMODEL + kc * 32 + c * 4);
    }
#pragma unroll
    for (int l = 0; l < 2; l++) {
      int idx = tid + l * 128, n = idx >> 2, c = idx & 3;
      cp16(st + PA_BYTES + n * 80 + c * 16,
           g_Wth + (size_t)(nb + n) * DMODEL + kc * 32 + c * 8);
    }
    CP_COMMIT();
  };

  issue(0);
  issue(1);

  float dot[2][4][4] = {};
  float wacc0 = 0.f, wacc1 = 0.f, wacc2 = 0.f, wacc3 = 0.f;
  const int wrow = tid >> 1;          // 0..63
  const int wkh = (tid & 1) * 16;     // k-half within chunk
  const int NKC = DMODEL / 32;  // 64

  for (int kc = 0; kc < NKC; kc++) {
    if (kc + 1 < NKC) { CP_WAIT(1); } else { CP_WAIT(0); }
    __syncthreads();  // all warps done with buf (kc+2)%3
    if (kc + 2 < NKC) issue(kc + 2);

    const char* st = smem + (kc % 3) * PSTG;
    const float* Fa = (const float*)st;
    const __half* Bh = (const __half*)(st + PA_BYTES);

    if (doW) {
      const float* arow = Fa + wrow * PAROW + wkh;
      const float4* wwp = (const float4*)(Ww + (kc * 32 + wkh) * 4);
#pragma unroll
      for (int kk = 0; kk < 16; kk++) {
        float xv = arow[kk];
        float4 w = wwp[kk];
        wacc0 = fmaf(xv, w.x, wacc0);
        wacc1 = fmaf(xv, w.y, wacc1);
        wacc2 = fmaf(xv, w.z, wacc2);
        wacc3 = fmaf(xv, w.w, wacc3);
      }
    }

#pragma unroll
    for (int ks = 0; ks < 2; ks++) {
      uint32_t ah[2][4], al[2][4];
#pragma unroll
      for (int mf = 0; mf < 2; mf++) {
        const float* p0 = Fa + (mwarp + mf * 16 + g) * PAROW + ks * 16 + 2 * q4;
        float2 v00 = *(const float2*)(p0);
        float2 v10 = *(const float2*)(p0 + 8 * PAROW);
        float2 v01 = *(const float2*)(p0 + 8);
        float2 v11 = *(const float2*)(p0 + 8 * PAROW + 8);
        split2h(v00.x, v00.y, ah[mf][0], al[mf][0]);
        split2h(v10.x, v10.y, ah[mf][1], al[mf][1]);
        split2h(v01.x, v01.y, ah[mf][2], al[mf][2]);
        split2h(v11.x, v11.y, ah[mf][3], al[mf][3]);
      }
#pragma unroll
      for (int p = 0; p < 2; p++) {
        uint32_t bh[4];
        ldmx4(bh, Bh + (nwarp + p * 16 + bRow) * PSP + ks * 16 + bCol);
#pragma unroll
        for (int mf = 0; mf < 2; mf++) {
          mma_f16(dot[mf][2 * p], ah[mf], bh[0], bh[1]);
          mma_f16(dot[mf][2 * p], al[mf], bh[0], bh[1]);
          mma_f16(dot[mf][2 * p + 1], ah[mf], bh[2], bh[3]);
          mma_f16(dot[mf][2 * p + 1], al[mf], bh[2], bh[3]);
        }
      }
    }
  }

  if (doW) {
    wacc0 += __shfl_xor_sync(0xffffffffu, wacc0, 1);
    wacc1 += __shfl_xor_sync(0xffffffffu, wacc1, 1);
    wacc2 += __shfl_xor_sync(0xffffffffu, wacc2, 1);
    wacc3 += __shfl_xor_sync(0xffffffffu, wacc3, 1);
    if ((tid & 1) == 0)
      *(float4*)&g_wI[(size_t)(m0 + wrow) * 4] =
          make_float4(wacc0, wacc1, wacc2, wacc3);
  }

  // epilogue: single fp16 store
#pragma unroll
  for (int mf = 0; mf < 2; mf++) {
#pragma unroll
    for (int nf = 0; nf < 4; nf++) {
      int grow = m0 + mwarp + mf * 16 + g;
      if (isQ) {
        int ncol = nb + nwarp + nf * 8 + q4 * 2;  // global Wq col (0..255)
        int head = ncol >> 6, hcol = ncol & 63;
        __half* Oh = g_qIh + ((size_t)head * ROWS + grow) * 64 + hcol;
        *(uint32_t*)Oh = cvt2h(dot[mf][nf][0], dot[mf][nf][1]);
        *(uint32_t*)(Oh + 8 * 64) = cvt2h(dot[mf][nf][2], dot[mf][nf][3]);
      } else {
        int ncol = nwarp + nf * 8 + q4 * 2;
        __half* Oh = g_kIh + (size_t)grow * 64 + ncol;
        *(uint32_t*)Oh = cvt2h(dot[mf][nf][0], dot[mf][nf][1]);
        *(uint32_t*)(Oh + 8 * 64) = cvt2h(dot[mf][nf][2], dot[mf][nf][3]);
      }
    }
  }
}

// ---------------------------------------------------------------------------
// Main: CTA 64q x 64k, 128 threads (4 warps, 2x2 of 32x32), 4 CTAs/SM.
// A (q head, fp16) double-buffered cp.async; B (k, fp16) fixed; per head:
// dot = q*k (single fp16 MMA) -> relu -> w-weighted accumulate.
// ---------------------------------------------------------------------------
#define MSP 72
#define MAB (64 * MSP * 2)                  // 9216
#define M_B (2 * MAB)                       // B at 2*MAB
#define M_WS (3 * MAB)
#define MAIN_SMEM (3 * MAB + 1024)          // 28672+1024

__global__ __launch_bounds__(128, 4) void main_mma_kernel(
    const float* __restrict__ wI, float* __restrict__ out) {
  extern __shared__ __align__(16) char smem[];
  float* ws = (float*)(smem + M_WS);

  const int tid = threadIdx.x, wid = tid >> 5, lane = tid & 31;
  const int g = lane >> 2, q4 = lane & 3;
  const int mwarp = (wid >> 1) * 32, nwarp = (wid & 1) * 32;
  const int b = blockIdx.z, q0 = blockIdx.y * 64, k0 = blockIdx.x * 64;

  const int aRow = (lane & 7) + (lane & 8);
  const int aCol = (lane & 16) ? 8 : 0;
  const int bRow = (lane & 7) + ((lane & 16) ? 8 : 0);
  const int bCol = (lane & 8) ? 8 : 0;

  auto issueA = [&](int h) {
    char* st = smem + (h & 1) * MAB;
    size_t base = ((size_t)h * ROWS + b * TQDIM + q0) * 64;
#pragma unroll
    for (int l = 0; l < 4; l++) {
      int idx = tid + l * 128, m = idx >> 3, c = idx & 7;
      cp16(st + m * 144 + c * 16, g_qIh + base + (size_t)m * 64 + c * 8);
    }
  };

  // prologue: group0 = B + A(0); group1 = A(1)
  {
    char* st = smem + M_B;
    size_t base = ((size_t)b * TKDIM + k0) * 64;
#pragma unroll
    for (int l = 0; l < 4; l++) {
      int idx = tid + l * 128, m = idx >> 3, c = idx & 7;
      cp16(st + m * 144 + c * 16, g_kIh + base + (size_t)m * 64 + c * 8);
    }
  }
  issueA(0);
  CP_COMMIT();
  issueA(1);
  CP_COMMIT();
  if (tid < 64)
    *(float4*)&ws[tid * 4] =
        *(const float4*)&wI[(size_t)(b * TQDIM + q0 + tid) * 4];

  const __half* Bh = (const __half*)(smem + M_B);

  float acc[2][4][4] = {};

  for (int h = 0; h < NHEADS; h++) {
    if (h + 1 < NHEADS) { CP_WAIT(1); } else { CP_WAIT(0); }
    __syncthreads();
    const __half* Ah = (const __half*)(smem + (h & 1) * MAB);

    float dot[2][4][4] = {};
#pragma unroll
    for (int ks = 0; ks < 4; ks++) {
      uint32_t ah[2][4];
#pragma unroll
      for (int mf = 0; mf < 2; mf++) {
        ldmx4(ah[mf], Ah + (mwarp + mf * 16 + aRow) * MSP + ks * 16 + aCol);
      }
#pragma unroll
      for (int p = 0; p < 2; p++) {
        uint32_t bh[4];
        ldmx4(bh, Bh + (nwarp + p * 16 + bRow) * MSP + ks * 16 + bCol);
#pragma unroll
        for (int mf = 0; mf < 2; mf++) {
          mma_f16(dot[mf][2 * p], ah[mf], bh[0], bh[1]);
          mma_f16(dot[mf][2 * p + 1], ah[mf], bh[2], bh[3]);
        }
      }
    }
    // relu + weighted accumulate
#pragma unroll
    for (int mf = 0; mf < 2; mf++) {
      float wa = ws[(mwarp + mf * 16 + g) * 4 + h];
      float wb = ws[(mwarp + mf * 16 + g + 8) * 4 + h];
#pragma unroll
      for (int nf = 0; nf < 4; nf++) {
        acc[mf][nf][0] = fmaf(wa, fmaxf(dot[mf][nf][0], 0.f), acc[mf][nf][0]);
        acc[mf][nf][1] = fmaf(wa, fmaxf(dot[mf][nf][1], 0.f), acc[mf][nf][1]);
        acc[mf][nf][2] = fmaf(wb, fmaxf(dot[mf][nf][2], 0.f), acc[mf][nf][2]);
        acc[mf][nf][3] = fmaf(wb, fmaxf(dot[mf][nf][3], 0.f), acc[mf][nf][3]);
      }
    }
    if (h + 2 < NHEADS) {
      __syncthreads();  // all warps done with buf (h&1)
      issueA(h + 2);
      CP_COMMIT();
    }
  }

  float* obase = out + (size_t)(b * TQDIM + q0) * TKDIM + k0;
#pragma unroll
  for (int mf = 0; mf < 2; mf++) {
    int r0 = mwarp + mf * 16 + g;
#pragma unroll
    for (int nf = 0; nf < 4; nf++) {
      int col = nwarp + nf * 8 + q4 * 2;
      *(float2*)&obase[(size_t)r0 * TKDIM + col] =
          make_float2(acc[mf][nf][0], acc[mf][nf][1]);
      *(float2*)&obase[(size_t)(r0 + 8) * TKDIM + col] =
          make_float2(acc[mf][nf][2], acc[mf][nf][3]);
    }
  }
}

// ---------------------------------------------------------------------------
extern "C" void kernel_launch(void* const* d_in, const int* in_sizes, int n_in,
                              void* d_out, int out_size) {
  const float* x_q = (const float*)d_in[0];
  const float* x_k = (const float*)d_in[1];
  const float* Wq = (const float*)d_in[2];
  const float* Ww = (const float*)d_in[3];
  const float* Wk = (const float*)d_in[4];
  float* out = (float*)d_out;

  float* wI;
  cudaGetSymbolAddress((void**)&wI, g_wI);

  cudaFuncSetAttribute(proj_kernel, cudaFuncAttributeMaxDynamicSharedMemorySize,
                       PROJ_SMEM);
  cudaFuncSetAttribute(main_mma_kernel,
                       cudaFuncAttributeMaxDynamicSharedMemorySize, MAIN_SMEM);

  prep_kernel<<<2560, 256>>>(Wq, Wk);
  proj_kernel<<<640, 128, PROJ_SMEM>>>(x_q, x_k, Ww);
  main_mma_kernel<<<dim3(TKDIM / 64, TQDIM / 64, 2), 128, MAIN_SMEM>>>(wI,
                                                                       out);
}

// round 17
// speedup vs baseline: 1.5470x; 1.0079x over previous
#include <cuda_runtime.h>
#include <cuda_fp16.h>
#include <cstdint>

// Shapes (fixed)
#define TQDIM 4096
#define TKDIM 4096
#define DMODEL 2048
#define NHEADS 4
#define ROWS 8192  // B*T

// Weight transpose, fp16; [n][k], n<256: Wq col, n>=256: Wk col
__device__ __half g_Wth[320 * DMODEL];
// Projection outputs, fp16; q head-major [h][row][64], k [row][64]
__device__ __half g_qIh[NHEADS * ROWS * 64];
__device__ __half g_kIh[ROWS * 64];
__device__ float g_wI[ROWS * 4];

// ---------------------------------------------------------------------------
// helpers
// ---------------------------------------------------------------------------
// pack two fp32 -> f16x2 (first arg -> low half), rn rounding
__device__ __forceinline__ uint32_t cvt2h(float lo, float hi) {
  uint32_t r;
  asm("cvt.rn.f16x2.f32 %0, %1, %2;" : "=r"(r) : "f"(hi), "f"(lo));
  return r;
}

__device__ __forceinline__ void mma_f16(float* c, const uint32_t* a,
                                        uint32_t b0, uint32_t b1) {
  asm volatile(
      "mma.sync.aligned.m16n8k16.row.col.f32.f16.f16.f32 "
      "{%0,%1,%2,%3}, {%4,%5,%6,%7}, {%8,%9}, {%0,%1,%2,%3};\n"
      : "+f"(c[0]), "+f"(c[1]), "+f"(c[2]), "+f"(c[3])
      : "r"(a[0]), "r"(a[1]), "r"(a[2]), "r"(a[3]), "r"(b0), "r"(b1));
}

__device__ __forceinline__ void ldmx4(uint32_t* r, const void* p) {
  uint32_t a = (uint32_t)__cvta_generic_to_shared(p);
  asm volatile(
      "ldmatrix.sync.aligned.m8n8.x4.shared.b16 {%0,%1,%2,%3}, [%4];"
      : "=r"(r[0]), "=r"(r[1]), "=r"(r[2]), "=r"(r[3])
      : "r"(a));
}

__device__ __forceinline__ void cp16(void* dst, const void* src) {
  uint32_t d = (uint32_t)__cvta_generic_to_shared(dst);
  asm volatile("cp.async.cg.shared.global [%0], [%1], 16;" :: "r"(d), "l"(src));
}
#define CP_COMMIT() asm volatile("cp.async.commit_group;" ::: "memory")
#define CP_WAIT(n) asm volatile("cp.async.wait_group %0;" :: "n"(n) : "memory")

// ---------------------------------------------------------------------------
// prep: Wt[n][k] = fp16(W[k][n]) (grid 2560)
// ---------------------------------------------------------------------------
__global__ __launch_bounds__(256) void prep_kernel(
    const float* __restrict__ Wq, const float* __restrict__ Wk) {
  int idx = blockIdx.x;        // 0..2559
  int n = idx >> 3;            // 0..319
  int k = (idx & 7) * 256 + threadIdx.x;
  float v =
      (n < 256) ? Wq[(size_t)k * 256 + n] : Wk[(size_t)k * 64 + (n - 256)];
  g_Wth[(size_t)n * DMODEL + k] = __float2half_rn(v);
}

// ---------------------------------------------------------------------------
// Projection: C = fp16(x) @ fp16(Wt)^T, single fp16 HMMA per frag pair.
// CTA 64 x 64, 4 warps (2x2 of 32x32), K-chunk 32, 3-stage cp.async ring,
// 4 CTAs/SM. A kept fp32 in smem; frag build = LDS.64 + cvt2h (no residual).
// q-CTAs with nb==0 also accumulate wI (fp32, full precision).
// Grid 640: blocks 0..511: q (m0=(bx>>2)*64, nb=(bx&3)*64); 512..639: k.
// ---------------------------------------------------------------------------
#define PSP 40                    // B tile stride in halves (80 B rows)
#define PAROW 36                  // A fp32 row stride in floats (144 B)
#define PA_BYTES (64 * PAROW * 4) // 9216
#define PB_BYTES (64 * 80)        // 5120
#define PSTG (PA_BYTES + PB_BYTES)      // 14336
#define PROJ_SMEM (3 * PSTG)            // 43008

__global__ __launch_bounds__(128, 4) void proj_kernel(
    const float* __restrict__ xq, const float* __restrict__ xk,
    const float* __restrict__ Ww) {
  extern __shared__ __align__(16) char smem[];
  const int bx = blockIdx.x;
  const bool isQ = bx < 512;
  const int m0 = isQ ? (bx >> 2) * 64 : (bx - 512) * 64;
  const int nb = isQ ? (bx & 3) * 64 : 256;  // Wt row base
  const float* A = isQ ? xq : xk;
  const bool doW = isQ && (bx & 3) == 0;

  const int tid = threadIdx.x, wid = tid >> 5, lane = tid & 31;
  const int g = lane >> 2, q4 = lane & 3;
  const int mwarp = (wid >> 1) * 32, nwarp = (wid & 1) * 32;

  const int bRow = (lane & 7) + ((lane & 16) ? 8 : 0);
  const int bCol = (lane & 8) ? 8 : 0;

  auto issue = [&](int kc) {
    char* st = smem + (kc % 3) * PSTG;
#pragma unroll
    for (int l = 0; l < 4; l++) {
      int idx = tid + l * 128, m = idx >> 3, c = idx & 7;
      cp16(st + m * 144 + c * 16,
           A + (size_t)(m0 + m) * DMODEL + kc * 32 + c * 4);
    }
#pragma unroll
    for (int l = 0; l < 2; l++) {
      int idx = tid + l * 128, n = idx >> 2, c = idx & 3;
      cp16(st + PA_BYTES + n * 80 + c * 16,
           g_Wth + (size_t)(nb + n) * DMODEL + kc * 32 + c * 8);
    }
    CP_COMMIT();
  };

  issue(0);
  issue(1);

  float dot[2][4][4] = {};
  float wacc0 = 0.f, wacc1 = 0.f, wacc2 = 0.f, wacc3 = 0.f;
  const int wrow = tid >> 1;          // 0..63
  const int wkh = (tid & 1) * 16;     // k-half within chunk
  const int NKC = DMODEL / 32;  // 64

  for (int kc = 0; kc < NKC; kc++) {
    if (kc + 1 < NKC) { CP_WAIT(1); } else { CP_WAIT(0); }
    __syncthreads();  // all warps done with buf (kc+2)%3
    if (kc + 2 < NKC) issue(kc + 2);

    const char* st = smem + (kc % 3) * PSTG;
    const float* Fa = (const float*)st;
    const __half* Bh = (const __half*)(st + PA_BYTES);

    if (doW) {
      const float* arow = Fa + wrow * PAROW + wkh;
      const float4* wwp = (const float4*)(Ww + (kc * 32 + wkh) * 4);
#pragma unroll
      for (int kk = 0; kk < 16; kk++) {
        float xv = arow[kk];
        float4 w = wwp[kk];
        wacc0 = fmaf(xv, w.x, wacc0);
        wacc1 = fmaf(xv, w.y, wacc1);
        wacc2 = fmaf(xv, w.z, wacc2);
        wacc3 = fmaf(xv, w.w, wacc3);
      }
    }

#pragma unroll
    for (int ks = 0; ks < 2; ks++) {
      uint32_t ah[2][4];
#pragma unroll
      for (int mf = 0; mf < 2; mf++) {
        const float* p0 = Fa + (mwarp + mf * 16 + g) * PAROW + ks * 16 + 2 * q4;
        float2 v00 = *(const float2*)(p0);
        float2 v10 = *(const float2*)(p0 + 8 * PAROW);
        float2 v01 = *(const float2*)(p0 + 8);
        float2 v11 = *(const float2*)(p0 + 8 * PAROW + 8);
        ah[mf][0] = cvt2h(v00.x, v00.y);
        ah[mf][1] = cvt2h(v10.x, v10.y);
        ah[mf][2] = cvt2h(v01.x, v01.y);
        ah[mf][3] = cvt2h(v11.x, v11.y);
      }
#pragma unroll
      for (int p = 0; p < 2; p++) {
        uint32_t bh[4];
        ldmx4(bh, Bh + (nwarp + p * 16 + bRow) * PSP + ks * 16 + bCol);
#pragma unroll
        for (int mf = 0; mf < 2; mf++) {
          mma_f16(dot[mf][2 * p], ah[mf], bh[0], bh[1]);
          mma_f16(dot[mf][2 * p + 1], ah[mf], bh[2], bh[3]);
        }
      }
    }
  }

  if (doW) {
    wacc0 += __shfl_xor_sync(0xffffffffu, wacc0, 1);
    wacc1 += __shfl_xor_sync(0xffffffffu, wacc1, 1);
    wacc2 += __shfl_xor_sync(0xffffffffu, wacc2, 1);
    wacc3 += __shfl_xor_sync(0xffffffffu, wacc3, 1);
    if ((tid & 1) == 0)
      *(float4*)&g_wI[(size_t)(m0 + wrow) * 4] =
          make_float4(wacc0, wacc1, wacc2, wacc3);
  }

  // epilogue: single fp16 store
#pragma unroll
  for (int mf = 0; mf < 2; mf++) {
#pragma unroll
    for (int nf = 0; nf < 4; nf++) {
      int grow = m0 + mwarp + mf * 16 + g;
      if (isQ) {
        int ncol = nb + nwarp + nf * 8 + q4 * 2;  // global Wq col (0..255)
        int head = ncol >> 6, hcol = ncol & 63;
        __half* Oh = g_qIh + ((size_t)head * ROWS + grow) * 64 + hcol;
        *(uint32_t*)Oh = cvt2h(dot[mf][nf][0], dot[mf][nf][1]);
        *(uint32_t*)(Oh + 8 * 64) = cvt2h(dot[mf][nf][2], dot[mf][nf][3]);
      } else {
        int ncol = nwarp + nf * 8 + q4 * 2;
        __half* Oh = g_kIh + (size_t)grow * 64 + ncol;
        *(uint32_t*)Oh = cvt2h(dot[mf][nf][0], dot[mf][nf][1]);
        *(uint32_t*)(Oh + 8 * 64) = cvt2h(dot[mf][nf][2], dot[mf][nf][3]);
      }
    }
  }
}

// ---------------------------------------------------------------------------
// Main: CTA 64q x 64k, 128 threads (4 warps, 2x2 of 32x32), 4 CTAs/SM.
// A (q head, fp16) double-buffered cp.async; B (k, fp16) fixed; per head:
// dot = q*k (single fp16 MMA) -> relu -> w-weighted accumulate.
// ---------------------------------------------------------------------------
#define MSP 72
#define MAB (64 * MSP * 2)                  // 9216
#define M_B (2 * MAB)                       // B at 2*MAB
#define M_WS (3 * MAB)
#define MAIN_SMEM (3 * MAB + 1024)

__global__ __launch_bounds__(128, 4) void main_mma_kernel(
    const float* __restrict__ wI, float* __restrict__ out) {
  extern __shared__ __align__(16) char smem[];
  float* ws = (float*)(smem + M_WS);

  const int tid = threadIdx.x, wid = tid >> 5, lane = tid & 31;
  const int g = lane >> 2, q4 = lane & 3;
  const int mwarp = (wid >> 1) * 32, nwarp = (wid & 1) * 32;
  const int b = blockIdx.z, q0 = blockIdx.y * 64, k0 = blockIdx.x * 64;

  const int aRow = (lane & 7) + (lane & 8);
  const int aCol = (lane & 16) ? 8 : 0;
  const int bRow = (lane & 7) + ((lane & 16) ? 8 : 0);
  const int bCol = (lane & 8) ? 8 : 0;

  auto issueA = [&](int h) {
    char* st = smem + (h & 1) * MAB;
    size_t base = ((size_t)h * ROWS + b * TQDIM + q0) * 64;
#pragma unroll
    for (int l = 0; l < 4; l++) {
      int idx = tid + l * 128, m = idx >> 3, c = idx & 7;
      cp16(st + m * 144 + c * 16, g_qIh + base + (size_t)m * 64 + c * 8);
    }
  };

  // prologue: group0 = B + A(0); group1 = A(1)
  {
    char* st = smem + M_B;
    size_t base = ((size_t)b * TKDIM + k0) * 64;
#pragma unroll
    for (int l = 0; l < 4; l++) {
      int idx = tid + l * 128, m = idx >> 3, c = idx & 7;
      cp16(st + m * 144 + c * 16, g_kIh + base + (size_t)m * 64 + c * 8);
    }
  }
  issueA(0);
  CP_COMMIT();
  issueA(1);
  CP_COMMIT();
  if (tid < 64)
    *(float4*)&ws[tid * 4] =
        *(const float4*)&wI[(size_t)(b * TQDIM + q0 + tid) * 4];

  const __half* Bh = (const __half*)(smem + M_B);

  float acc[2][4][4] = {};

  for (int h = 0; h < NHEADS; h++) {
    if (h + 1 < NHEADS) { CP_WAIT(1); } else { CP_WAIT(0); }
    __syncthreads();
    const __half* Ah = (const __half*)(smem + (h & 1) * MAB);

    float dot[2][4][4] = {};
#pragma unroll
    for (int ks = 0; ks < 4; ks++) {
      uint32_t ah[2][4];
#pragma unroll
      for (int mf = 0; mf < 2; mf++) {
        ldmx4(ah[mf], Ah + (mwarp + mf * 16 + aRow) * MSP + ks * 16 + aCol);
      }
#pragma unroll
      for (int p = 0; p < 2; p++) {
        uint32_t bh[4];
        ldmx4(bh, Bh + (nwarp + p * 16 + bRow) * MSP + ks * 16 + bCol);
#pragma unroll
        for (int mf = 0; mf < 2; mf++) {
          mma_f16(dot[mf][2 * p], ah[mf], bh[0], bh[1]);
          mma_f16(dot[mf][2 * p + 1], ah[mf], bh[2], bh[3]);
        }
      }
    }
    // relu + weighted accumulate
#pragma unroll
    for (int mf = 0; mf < 2; mf++) {
      float wa = ws[(mwarp + mf * 16 + g) * 4 + h];
      float wb = ws[(mwarp + mf * 16 + g + 8) * 4 + h];
#pragma unroll
      for (int nf = 0; nf < 4; nf++) {
        acc[mf][nf][0] = fmaf(wa, fmaxf(dot[mf][nf][0], 0.f), acc[mf][nf][0]);
        acc[mf][nf][1] = fmaf(wa, fmaxf(dot[mf][nf][1], 0.f), acc[mf][nf][1]);
        acc[mf][nf][2] = fmaf(wb, fmaxf(dot[mf][nf][2], 0.f), acc[mf][nf][2]);
        acc[mf][nf][3] = fmaf(wb, fmaxf(dot[mf][nf][3], 0.f), acc[mf][nf][3]);
      }
    }
    if (h + 2 < NHEADS) {
      __syncthreads();  // all warps done with buf (h&1)
      issueA(h + 2);
      CP_COMMIT();
    }
  }

  float* obase = out + (size_t)(b * TQDIM + q0) * TKDIM + k0;
#pragma unroll
  for (int mf = 0; mf < 2; mf++) {
    int r0 = mwarp + mf * 16 + g;
#pragma unroll
    for (int nf = 0; nf < 4; nf++) {
      int col = nwarp + nf * 8 + q4 * 2;
      *(float2*)&obase[(size_t)r0 * TKDIM + col] =
          make_float2(acc[mf][nf][0], acc[mf][nf][1]);
      *(float2*)&obase[(size_t)(r0 + 8) * TKDIM + col] =
          make_float2(acc[mf][nf][2], acc[mf][nf][3]);
    }
  }
}

// ---------------------------------------------------------------------------
extern "C" void kernel_launch(void* const* d_in, const int* in_sizes, int n_in,
                              void* d_out, int out_size) {
  const float* x_q = (const float*)d_in[0];
  const float* x_k = (const float*)d_in[1];
  const float* Wq = (const float*)d_in[2];
  const float* Ww = (const float*)d_in[3];
  const float* Wk = (const float*)d_in[4];
  float* out = (float*)d_out;

  float* wI;
  cudaGetSymbolAddress((void**)&wI, g_wI);

  cudaFuncSetAttribute(proj_kernel, cudaFuncAttributeMaxDynamicSharedMemorySize,
                       PROJ_SMEM);
  cudaFuncSetAttribute(main_mma_kernel,
                       cudaFuncAttributeMaxDynamicSharedMemorySize, MAIN_SMEM);

  prep_kernel<<<2560, 256>>>(Wq, Wk);
  proj_kernel<<<640, 128, PROJ_SMEM>>>(x_q, x_k, Ww);
  main_mma_kernel<<<dim3(TKDIM / 64, TQDIM / 64, 2), 128, MAIN_SMEM>>>(wI,
                                                                       out);
}